// round 1
// baseline (speedup 1.0000x reference)
#include <cuda_runtime.h>
#include <cstdint>
#include <cstddef>

// Problem constants
constexpr int B_ = 4;
constexpr int C_ = 128;
constexpr int N_ = 4096;
constexpr int K_ = 32;

// ---------------------------------------------------------------------------
// Scratch (device globals; allocation at module load is the sanctioned path)
// ---------------------------------------------------------------------------
__device__ float sc_feat1[(size_t)B_ * 64 * N_];          //  4 MB, relu(W_feat@feat+b)
__device__ float sc_g1  [(size_t)B_ * 64 * N_ * K_];      // 128 MB, relu(W_grp@gf+b)
__device__ float sc_y3  [(size_t)B_ * C_ * N_ * K_];      // 256 MB, W_fo@gfo+b (pre-norm)
__device__ float sc_x1  [(size_t)B_ * C_ * N_ * K_];      // 256 MB, relu(W_wc1@x+b)

// Group-norm statistics: slot 0 = gn1, slot 1 = gn2, slot 2 = gn3
__device__ double g_sum  [3][B_][C_];
__device__ double g_sq   [3][B_][C_];
__device__ float  g_scale[3][B_][C_];
__device__ float  g_shift[3][B_][C_];

// ---------------------------------------------------------------------------
// Packed f32x2 helpers (Blackwell FFMA2: 2x fp32 FMA throughput vs FFMA)
// ---------------------------------------------------------------------------
__device__ __forceinline__ unsigned long long pack2(float lo, float hi) {
    unsigned long long r;
    asm("mov.b64 %0, {%1, %2};" : "=l"(r) : "f"(lo), "f"(hi));
    return r;
}
__device__ __forceinline__ void fma2(unsigned long long& d,
                                     unsigned long long a,
                                     unsigned long long b) {
    asm("fma.rn.f32x2 %0, %1, %2, %0;" : "+l"(d) : "l"(a), "l"(b));
}
__device__ __forceinline__ void unpack2(unsigned long long v, float& lo, float& hi) {
    asm("mov.b64 {%0, %1}, %2;" : "=f"(lo), "=f"(hi) : "l"(v));
}

// ---------------------------------------------------------------------------
__global__ void zero_stats_k() {
    int t = blockIdx.x * blockDim.x + threadIdx.x;
    if (t < 3 * B_ * C_) {
        (&g_sum[0][0][0])[t] = 0.0;
        (&g_sq [0][0][0])[t] = 0.0;
    }
}

// ---------------------------------------------------------------------------
// feat1 = relu(W_feat @ feat + b_feat)  -> sc_feat1, + gn1 stats (ch 0..63, x K)
// grid (N/32, B), 256 threads
// ---------------------------------------------------------------------------
__global__ void __launch_bounds__(256) feat1_k(const float* __restrict__ feat,
                                               const float* __restrict__ Wf,
                                               const float* __restrict__ bf) {
    __shared__ float Ws[64 * 128];   // 32 KB
    __shared__ float Fs[128 * 32];   // 16 KB
    const int b  = blockIdx.y;
    const int n0 = blockIdx.x * 32;
    const int tid = threadIdx.x;

    for (int idx = tid; idx < 64 * 128; idx += 256) Ws[idx] = Wf[idx];
    for (int idx = tid; idx < 128 * 32; idx += 256) {
        int c = idx >> 5, jj = idx & 31;
        Fs[idx] = feat[(size_t)(b * 128 + c) * N_ + n0 + jj];
    }
    __syncthreads();

    const int jj = tid & 31;
    const int w  = tid >> 5;     // 8 warps -> o = w*8 + oi
    float acc[8];
#pragma unroll
    for (int oi = 0; oi < 8; ++oi) acc[oi] = __ldg(bf + w * 8 + oi);
#pragma unroll 4
    for (int c = 0; c < 128; ++c) {
        float x = Fs[c * 32 + jj];
#pragma unroll
        for (int oi = 0; oi < 8; ++oi)
            acc[oi] = fmaf(Ws[(w * 8 + oi) * 128 + c], x, acc[oi]);
    }
#pragma unroll
    for (int oi = 0; oi < 8; ++oi) {
        int o = w * 8 + oi;
        float v = fmaxf(acc[oi], 0.f);
        sc_feat1[(size_t)(b * 64 + o) * N_ + n0 + jj] = v;
        float s = v, q = v * v;
#pragma unroll
        for (int off = 16; off; off >>= 1) {
            s += __shfl_xor_sync(0xffffffffu, s, off);
            q += __shfl_xor_sync(0xffffffffu, q, off);
        }
        if (jj == 0) {   // broadcast over K -> weight 32
            atomicAdd(&g_sum[0][b][o], (double)(32.0f * s));
            atomicAdd(&g_sq [0][b][o], (double)(32.0f * q));
        }
    }
}

// ---------------------------------------------------------------------------
// Generic register-tiled GEMM stage.
//   MODE 0: g1  = relu(W_grp @ gf  + b)   O=64  COLS=256 -> sc_g1, stats gn1 ch64+
//   MODE 1: y3  =      W_fo  @ gfo + b    O=128 COLS=128 -> sc_y3, stats gn3
//   MODE 2: x1  = relu(W_wc1 @ gn1(concat(feat1, g1)) + b) -> sc_x1, stats gn2
//   MODE 3: scores = W_wc2 @ gn2(x1) + b; masked softmax over K;
//           out = sum_k relu(gn3(y3)) * weight                 -> d_out
// ---------------------------------------------------------------------------
struct Ptrs {
    const float* X;
    const float* W;
    const float* bias;
    const int*   count;
    float*       out;
};

template <int MODE>
__global__ void __launch_bounds__(256, 1) gemm_k(Ptrs p) {
    constexpr int O    = (MODE == 0) ? 64 : 128;
    constexpr int COLS = 16384 / O;        // 256 (MODE0) or 128
    constexpr int JT   = COLS / 8;         // 32 or 16

    extern __shared__ float sm[];
    float* Wt = sm;                        // [128][O]  (c-major)
    float* Xs = sm + 128 * O;              // [128][COLS]

    const int tid = threadIdx.x;
    const int b   = blockIdx.y;
    const int n0  = blockIdx.x * (COLS / 32);

    // ---- load W transposed -------------------------------------------------
    for (int idx = tid; idx < 128 * O; idx += 256) {
        int o = idx >> 7, c = idx & 127;
        Wt[c * O + o] = p.W[idx];
    }
    // ---- load/build X tile -------------------------------------------------
    if (MODE == 0 || MODE == 1) {
        for (int idx = tid; idx < 128 * (COLS / 4); idx += 256) {
            int c = idx / (COLS / 4), q = idx % (COLS / 4);
            float4 v = *(const float4*)(p.X + ((size_t)(b * 128 + c) * N_ + n0) * K_ + q * 4);
            *(float4*)(Xs + c * COLS + q * 4) = v;
        }
    } else if (MODE == 2) {
        // channels 64..127 from sc_g1 with gn1 affine
        for (int idx = tid; idx < 64 * (COLS / 4); idx += 256) {
            int c = idx / (COLS / 4), q = idx % (COLS / 4);
            int ch = 64 + c;
            float sc = g_scale[0][b][ch], sh = g_shift[0][b][ch];
            float4 v = *(const float4*)(sc_g1 + ((size_t)(b * 64 + c) * N_ + n0) * K_ + q * 4);
            v.x = fmaf(v.x, sc, sh); v.y = fmaf(v.y, sc, sh);
            v.z = fmaf(v.z, sc, sh); v.w = fmaf(v.w, sc, sh);
            *(float4*)(Xs + ch * COLS + q * 4) = v;
        }
        // channels 0..63 broadcast feat1 with gn1 affine
        for (int idx = tid; idx < 64 * COLS; idx += 256) {
            int c = idx / COLS, col = idx % COLS;
            float sc = g_scale[0][b][c], sh = g_shift[0][b][c];
            float v = sc_feat1[(size_t)(b * 64 + c) * N_ + n0 + (col >> 5)];
            Xs[c * COLS + col] = fmaf(v, sc, sh);
        }
    } else { // MODE 3: gn2 affine of sc_x1
        for (int idx = tid; idx < 128 * (COLS / 4); idx += 256) {
            int c = idx / (COLS / 4), q = idx % (COLS / 4);
            float sc = g_scale[1][b][c], sh = g_shift[1][b][c];
            float4 v = *(const float4*)(sc_x1 + ((size_t)(b * 128 + c) * N_ + n0) * K_ + q * 4);
            v.x = fmaf(v.x, sc, sh); v.y = fmaf(v.y, sc, sh);
            v.z = fmaf(v.z, sc, sh); v.w = fmaf(v.w, sc, sh);
            *(float4*)(Xs + c * COLS + q * 4) = v;
        }
    }
    __syncthreads();

    // ---- 8x8 micro-tile GEMM with packed f32x2 FMA -------------------------
    const int i = tid / JT;
    const int j = tid % JT;

    unsigned long long acc[4][8];
#pragma unroll
    for (int m = 0; m < 4; ++m)
#pragma unroll
        for (int n = 0; n < 8; ++n) acc[m][n] = 0ull;

    const float* wa = Wt + i * 4;
    const float* wb = Wt + i * 4 + O / 2;
    const float* xa = Xs + j * 4;
    const float* xb = Xs + j * 4 + COLS / 2;

#pragma unroll 4
    for (int c = 0; c < 128; ++c) {
        float4 a0 = *(const float4*)(wa + c * O);
        float4 a1 = *(const float4*)(wb + c * O);
        float4 b0 = *(const float4*)(xa + c * COLS);
        float4 b1 = *(const float4*)(xb + c * COLS);
        unsigned long long ap[4];
        ap[0] = *(const unsigned long long*)&a0.x;
        ap[1] = *(const unsigned long long*)&a0.z;
        ap[2] = *(const unsigned long long*)&a1.x;
        ap[3] = *(const unsigned long long*)&a1.z;
        float bv[8] = {b0.x, b0.y, b0.z, b0.w, b1.x, b1.y, b1.z, b1.w};
        unsigned long long bs[8];
#pragma unroll
        for (int n = 0; n < 8; ++n) bs[n] = pack2(bv[n], bv[n]);
#pragma unroll
        for (int m = 0; m < 4; ++m)
#pragma unroll
            for (int n = 0; n < 8; ++n) fma2(acc[m][n], ap[m], bs[n]);
    }

    // unpack: rows r(mi) = i*4 + (mi&3) + (mi>>2)*(O/2)
    float accf[8][8];
#pragma unroll
    for (int m = 0; m < 4; ++m)
#pragma unroll
        for (int n = 0; n < 8; ++n) {
            float lo, hi;
            unpack2(acc[m][n], lo, hi);
            accf[(m & 1) * 2 + (m >> 1) * 4 + 0][n] = lo;
            accf[(m & 1) * 2 + (m >> 1) * 4 + 1][n] = hi;
        }
    // NOTE on mapping: m=0 -> rows i*4+0/1 ; m=1 -> i*4+2/3 ; m=2 -> +O/2 0/1 ; m=3 -> +O/2 2/3
    // accf index mi: (m&1)*2 + (m>>1)*4 + lohi  gives mi order 0,1,2,3,4,5,6,7 matching
    // r(mi) = i*4 + (mi&3) + (mi>>2)*(O/2)

    if (MODE != 3) {
        constexpr int SLOT  = (MODE == 0) ? 0 : ((MODE == 2) ? 1 : 2);
        constexpr int CHOFF = (MODE == 0) ? 64 : 0;
        float* dst = (MODE == 0) ? sc_g1 : ((MODE == 1) ? sc_y3 : sc_x1);
#pragma unroll
        for (int mi = 0; mi < 8; ++mi) {
            int r = i * 4 + (mi & 3) + (mi >> 2) * (O / 2);
            float bvv = __ldg(p.bias + r);
            float vrow[8];
            float s = 0.f, q = 0.f;
#pragma unroll
            for (int n = 0; n < 8; ++n) {
                float v = accf[mi][n] + bvv;
                if (MODE != 1) v = fmaxf(v, 0.f);
                vrow[n] = v; s += v; q += v * v;
            }
            size_t base = ((size_t)(b * O + r) * N_ + n0) * K_;
            *(float4*)(dst + base + j * 4)            = make_float4(vrow[0], vrow[1], vrow[2], vrow[3]);
            *(float4*)(dst + base + j * 4 + COLS / 2) = make_float4(vrow[4], vrow[5], vrow[6], vrow[7]);
#pragma unroll
            for (int off = JT / 2; off > 0; off >>= 1) {
                s += __shfl_xor_sync(0xffffffffu, s, off);
                q += __shfl_xor_sync(0xffffffffu, q, off);
            }
            if (j == 0) {
                atomicAdd(&g_sum[SLOT][b][CHOFF + r], (double)s);
                atomicAdd(&g_sq [SLOT][b][CHOFF + r], (double)q);
            }
        }
    } else {
        // ---- fused scores -> softmax -> weighted sum of gfo -----------------
        __syncthreads();                 // everyone done reading Wt
        float* Ss = Wt;                  // reuse 64 KB as score tile [128][128]
#pragma unroll
        for (int mi = 0; mi < 8; ++mi) {
            int r = i * 4 + (mi & 3) + (mi >> 2) * 64;
            float bvv = __ldg(p.bias + r);
#pragma unroll
            for (int n = 0; n < 8; ++n) {
                int cl = j * 4 + (n & 3) + (n >> 2) * 64;
                Ss[r * 128 + cl] = accf[mi][n] + bvv;
            }
        }
        __syncthreads();

        const int w = tid >> 5, k = tid & 31;
        for (int rho = w; rho < 512; rho += 8) {
            int c  = rho >> 2;
            int no = rho & 3;
            int n  = n0 + no;
            int cnt = p.count[b * N_ + n];
            if (cnt < 1) cnt = 1;
            float v  = Ss[c * 128 + no * 32 + k];
            float mv = (k < cnt) ? v : -1e9f;
            float mx = mv;
#pragma unroll
            for (int off = 16; off; off >>= 1)
                mx = fmaxf(mx, __shfl_xor_sync(0xffffffffu, mx, off));
            float e = __expf(mv - mx);
            float y = sc_y3[((size_t)(b * 128 + c) * N_ + n) * K_ + k];
            float gfo = fmaxf(fmaf(g_scale[2][b][c], y, g_shift[2][b][c]), 0.f);
            float num = e * gfo, den = e;
#pragma unroll
            for (int off = 16; off; off >>= 1) {
                num += __shfl_xor_sync(0xffffffffu, num, off);
                den += __shfl_xor_sync(0xffffffffu, den, off);
            }
            if (k == 0)
                p.out[(size_t)(b * 128 + c) * N_ + n] = num / den;
        }
    }
}

// ---------------------------------------------------------------------------
// Turn accumulated (sum, sumsq) into per-(b,channel) affine scale/shift.
// ---------------------------------------------------------------------------
__global__ void finalize_k(int slot, const float* __restrict__ wgn,
                           const float* __restrict__ bgn) {
    int t = threadIdx.x;                  // 512 threads: b = t/128, c = t%128
    int b = t >> 7, c = t & 127;
    int g = (c >> 2) << 2;
    double s = g_sum[slot][b][g] + g_sum[slot][b][g + 1] +
               g_sum[slot][b][g + 2] + g_sum[slot][b][g + 3];
    double q = g_sq[slot][b][g] + g_sq[slot][b][g + 1] +
               g_sq[slot][b][g + 2] + g_sq[slot][b][g + 3];
    const double cnte = 4.0 * N_ * K_;
    double mu  = s / cnte;
    double var = q / cnte - mu * mu;
    float rstd = (float)(1.0 / sqrt(var + 1e-5));
    float sc   = wgn[c] * rstd;
    g_scale[slot][b][c] = sc;
    g_shift[slot][b][c] = bgn[c] - (float)mu * sc;
}

// ---------------------------------------------------------------------------
extern "C" void kernel_launch(void* const* d_in, const int* in_sizes, int n_in,
                              void* d_out, int out_size) {
    const float* feat   = (const float*)d_in[0];
    const float* gf     = (const float*)d_in[1];
    const float* gfo    = (const float*)d_in[2];
    const int*   count  = (const int*)  d_in[3];
    const float* W_feat = (const float*)d_in[4];
    const float* b_feat = (const float*)d_in[5];
    const float* W_grp  = (const float*)d_in[6];
    const float* b_grp  = (const float*)d_in[7];
    const float* gn1_w  = (const float*)d_in[8];
    const float* gn1_b  = (const float*)d_in[9];
    const float* W_wc1  = (const float*)d_in[10];
    const float* b_wc1  = (const float*)d_in[11];
    const float* gn2_w  = (const float*)d_in[12];
    const float* gn2_b  = (const float*)d_in[13];
    const float* W_wc2  = (const float*)d_in[14];
    const float* b_wc2  = (const float*)d_in[15];
    const float* W_fo   = (const float*)d_in[16];
    const float* b_fo   = (const float*)d_in[17];
    const float* gn3_w  = (const float*)d_in[18];
    const float* gn3_b  = (const float*)d_in[19];
    float* out = (float*)d_out;

    const int smem0 = (128 * 64 + 128 * 256) * 4;   // 160 KB (MODE 0)
    const int smem1 = (128 * 128 + 128 * 128) * 4;  // 128 KB (MODE 1/2/3)
    cudaFuncSetAttribute(gemm_k<0>, cudaFuncAttributeMaxDynamicSharedMemorySize, smem0);
    cudaFuncSetAttribute(gemm_k<1>, cudaFuncAttributeMaxDynamicSharedMemorySize, smem1);
    cudaFuncSetAttribute(gemm_k<2>, cudaFuncAttributeMaxDynamicSharedMemorySize, smem1);
    cudaFuncSetAttribute(gemm_k<3>, cudaFuncAttributeMaxDynamicSharedMemorySize, smem1);

    zero_stats_k<<<2, 1024>>>();
    feat1_k<<<dim3(N_ / 32, B_), 256>>>(feat, W_feat, b_feat);

    { Ptrs p{gf,  W_grp, b_grp, nullptr, nullptr};
      gemm_k<0><<<dim3(N_ / 8, B_), 256, smem0>>>(p); }          // g1 + gn1 stats
    { Ptrs p{gfo, W_fo,  b_fo,  nullptr, nullptr};
      gemm_k<1><<<dim3(N_ / 4, B_), 256, smem1>>>(p); }          // y3 + gn3 stats

    finalize_k<<<1, 512>>>(0, gn1_w, gn1_b);
    finalize_k<<<1, 512>>>(2, gn3_w, gn3_b);

    { Ptrs p{nullptr, W_wc1, b_wc1, nullptr, nullptr};
      gemm_k<2><<<dim3(N_ / 4, B_), 256, smem1>>>(p); }          // x1 + gn2 stats

    finalize_k<<<1, 512>>>(1, gn2_w, gn2_b);

    { Ptrs p{nullptr, W_wc2, b_wc2, count, out};
      gemm_k<3><<<dim3(N_ / 4, B_), 256, smem1>>>(p); }          // scores->softmax->out
}

// round 3
// speedup vs baseline: 2.9800x; 2.9800x over previous
#include <cuda_runtime.h>
#include <cuda_bf16.h>
#include <cstdint>
#include <cstddef>

// ---------------------------------------------------------------------------
constexpr int B_ = 4;
constexpr int N_ = 4096;
constexpr int K_ = 32;
constexpr int CPB = N_ * K_;              // 131072 columns per batch
constexpr int TILES = B_ * (CPB / 128);   // 4096 tiles of 128 columns

// ---------------------------------------------------------------------------
// Scratch
// ---------------------------------------------------------------------------
__device__ float sc_feat1[(size_t)B_ * 64 * N_];
__device__ float sc_g1  [(size_t)B_ * 64 * CPB];
__device__ float sc_y3  [(size_t)B_ * 128 * CPB];
__device__ float sc_x1  [(size_t)B_ * 128 * CPB];

__device__ double g_sum  [3][B_][128];
__device__ double g_sq   [3][B_][128];
__device__ float  g_scale[3][B_][128];
__device__ float  g_shift[3][B_][128];

// ---------------------------------------------------------------------------
__device__ __forceinline__ uint32_t smem_to_u32(const void* p) {
    uint32_t a;
    asm("{ .reg .u64 t; cvta.to.shared.u64 t, %1; cvt.u32.u64 %0, t; }"
        : "=r"(a) : "l"(p));
    return a;
}
__device__ __forceinline__ void cp_async16(uint32_t dst, const void* src) {
    asm volatile("cp.async.cg.shared.global [%0], [%1], 16;" :: "r"(dst), "l"(src));
}
#define CP_COMMIT() asm volatile("cp.async.commit_group;" ::: "memory")
#define CP_WAIT0()  asm volatile("cp.async.wait_group 0;" ::: "memory")

#define MMA_BF16(d, a0, a1, a2, a3, b0, b1) \
    asm volatile("mma.sync.aligned.m16n8k16.row.col.f32.bf16.bf16.f32 " \
        "{%0,%1,%2,%3},{%4,%5,%6,%7},{%8,%9},{%0,%1,%2,%3};" \
        : "+f"((d)[0]), "+f"((d)[1]), "+f"((d)[2]), "+f"((d)[3]) \
        : "r"(a0), "r"(a1), "r"(a2), "r"(a3), "r"(b0), "r"(b1))

// bf16 2-way split of a float pair -> packed bf16x2 hi and lo
__device__ __forceinline__ void split2(float x0, float x1, uint32_t& hi, uint32_t& lo) {
    __nv_bfloat162 h = __float22bfloat162_rn(make_float2(x0, x1));
    float r0 = x0 - __bfloat162float(h.x);
    float r1 = x1 - __bfloat162float(h.y);
    __nv_bfloat162 l = __float22bfloat162_rn(make_float2(r0, r1));
    hi = *(uint32_t*)&h;
    lo = *(uint32_t*)&l;
}

// ---------------------------------------------------------------------------
__global__ void zero_stats_k() {
    int t = blockIdx.x * blockDim.x + threadIdx.x;
    if (t < 3 * B_ * 128) {
        (&g_sum[0][0][0])[t] = 0.0;
        (&g_sq [0][0][0])[t] = 0.0;
    }
}

// ---------------------------------------------------------------------------
__global__ void __launch_bounds__(256) feat1_k(const float* __restrict__ feat,
                                               const float* __restrict__ Wf,
                                               const float* __restrict__ bf) {
    __shared__ float Ws[64 * 128];
    __shared__ float Fs[128 * 32];
    const int b  = blockIdx.y;
    const int n0 = blockIdx.x * 32;
    const int tid = threadIdx.x;

    for (int idx = tid; idx < 64 * 128; idx += 256) Ws[idx] = Wf[idx];
    for (int idx = tid; idx < 128 * 32; idx += 256) {
        int c = idx >> 5, jj = idx & 31;
        Fs[idx] = feat[(size_t)(b * 128 + c) * N_ + n0 + jj];
    }
    __syncthreads();

    const int jj = tid & 31;
    const int w  = tid >> 5;
    float acc[8];
#pragma unroll
    for (int oi = 0; oi < 8; ++oi) acc[oi] = __ldg(bf + w * 8 + oi);
#pragma unroll 4
    for (int c = 0; c < 128; ++c) {
        float x = Fs[c * 32 + jj];
#pragma unroll
        for (int oi = 0; oi < 8; ++oi)
            acc[oi] = fmaf(Ws[(w * 8 + oi) * 128 + c], x, acc[oi]);
    }
#pragma unroll
    for (int oi = 0; oi < 8; ++oi) {
        int o = w * 8 + oi;
        float v = fmaxf(acc[oi], 0.f);
        sc_feat1[(size_t)(b * 64 + o) * N_ + n0 + jj] = v;
        float s = v, q = v * v;
#pragma unroll
        for (int off = 16; off; off >>= 1) {
            s += __shfl_xor_sync(0xffffffffu, s, off);
            q += __shfl_xor_sync(0xffffffffu, q, off);
        }
        if (jj == 0) {
            atomicAdd(&g_sum[0][b][o], (double)(32.0f * s));
            atomicAdd(&g_sq [0][b][o], (double)(32.0f * q));
        }
    }
}

// ---------------------------------------------------------------------------
// HMMA (mma.sync bf16-split) GEMM stages; persistent CTAs with cp.async pipe.
//   MODE 0: g1 = relu(W_grp@gf + b)           O=64,  stats gn1 (ch 64+)
//   MODE 1: y3 = W_fo@gfo + b                 O=128, stats gn3 (no relu)
//   MODE 2: x1 = relu(W_wc1@gn1(concat) + b)  O=128, stats gn2
//   MODE 3: scores=W_wc2@gn2(x1); masked softmax; out = sum_k relu(gn3(y3))*w
// ---------------------------------------------------------------------------
struct Ptrs {
    const float* X;
    const float* W;
    const float* bias;
    const int*   count;
    float*       out;
};

template <int MODE>
__global__ void __launch_bounds__(256, 1) hmma_k(Ptrs p) {
    constexpr int O    = (MODE == 0) ? 64 : 128;
    constexpr int WR   = (MODE == 0) ? 2 : 4;      // warp rows
    constexpr int WC   = 8 / WR;                   // warp cols
    constexpr int CW   = 128 / WC;                 // cols per warp (32 or 64)
    constexpr int NT   = CW / 8;                   // n8 tiles per warp (4 or 8)
    constexpr int LDB  = 68;                       // u32 per k-row (pad 4)
    constexpr int CH   = (MODE == 2) ? 64 : 128;   // staged channels
    constexpr int CHS  = (MODE == 2) ? 64 : 128;   // src channel stride count

    extern __shared__ char smem[];
    uint32_t* Ah = (uint32_t*)smem;            // [O][LDB]
    uint32_t* Al = Ah + O * LDB;
    uint32_t* Bh = Al + O * LDB;               // [128 cols][LDB]
    uint32_t* Bl = Bh + 128 * LDB;
    float* stage = (float*)(Bl + 128 * LDB);   // [CH][128] fp32
    const uint32_t stage_u = smem_to_u32(stage);

    const int tid = threadIdx.x;
    const int wid = tid >> 5, lane = tid & 31;
    const int wrow = wid / WC, wcol = wid % WC;
    const int lq = lane >> 2, lr = lane & 3;   // quad id, quad lane

    const float* src = (MODE == 0 || MODE == 1) ? p.X : ((MODE == 2) ? sc_g1 : sc_x1);

    // ---- convert weights once -------------------------------------------
    for (int idx = tid; idx < O * 32; idx += 256) {
        int r = idx >> 5, c4 = (idx & 31) * 4;
        float4 w = *(const float4*)(p.W + r * 128 + c4);
        uint32_t h0, l0, h1, l1;
        split2(w.x, w.y, h0, l0);
        split2(w.z, w.w, h1, l1);
        Ah[r * LDB + c4 / 2] = h0; Ah[r * LDB + c4 / 2 + 1] = h1;
        Al[r * LDB + c4 / 2] = l0; Al[r * LDB + c4 / 2 + 1] = l1;
    }

    auto load_async = [&](int t) {
        int b = t >> 10, colbase = (t & 1023) << 7;
        for (int idx = tid; idx < CH * 32; idx += 256) {
            int ch = idx >> 5, c4 = (idx & 31) * 4;
            const float* s = src + ((size_t)(b * CHS + ch)) * CPB + colbase + c4;
            cp_async16(stage_u + (uint32_t)(ch * 128 + c4) * 4u, s);
        }
        CP_COMMIT();
    };

    auto convert = [&](int t) {
        int b = t >> 10, colbase = (t & 1023) << 7;
        for (int idx = tid; idx < CH * 16; idx += 256) {
            int cp2 = idx >> 5;              // channel pair within staged block
            int c4  = (idx & 31) * 4;
            int ch  = cp2 * 2;
            float4 a = *(const float4*)(stage + ch * 128 + c4);
            float4 c = *(const float4*)(stage + (ch + 1) * 128 + c4);
            int kpair = cp2;                 // u32 k-index in B tile
            if (MODE == 2) {
                int cc = 64 + ch;
                float s0 = g_scale[0][b][cc],     h0 = g_shift[0][b][cc];
                float s1 = g_scale[0][b][cc + 1], h1 = g_shift[0][b][cc + 1];
                a.x = fmaf(a.x, s0, h0); a.y = fmaf(a.y, s0, h0);
                a.z = fmaf(a.z, s0, h0); a.w = fmaf(a.w, s0, h0);
                c.x = fmaf(c.x, s1, h1); c.y = fmaf(c.y, s1, h1);
                c.z = fmaf(c.z, s1, h1); c.w = fmaf(c.w, s1, h1);
                kpair = 32 + cp2;            // concat channels 64..127
            } else if (MODE == 3) {
                float s0 = g_scale[1][b][ch],     h0 = g_shift[1][b][ch];
                float s1 = g_scale[1][b][ch + 1], h1 = g_shift[1][b][ch + 1];
                a.x = fmaf(a.x, s0, h0); a.y = fmaf(a.y, s0, h0);
                a.z = fmaf(a.z, s0, h0); a.w = fmaf(a.w, s0, h0);
                c.x = fmaf(c.x, s1, h1); c.y = fmaf(c.y, s1, h1);
                c.z = fmaf(c.z, s1, h1); c.w = fmaf(c.w, s1, h1);
            }
            float av[4] = {a.x, a.y, a.z, a.w};
            float cv[4] = {c.x, c.y, c.z, c.w};
#pragma unroll
            for (int j = 0; j < 4; ++j) {
                uint32_t hi, lo;
                split2(av[j], cv[j], hi, lo);
                Bh[(c4 + j) * LDB + kpair] = hi;
                Bl[(c4 + j) * LDB + kpair] = lo;
            }
        }
        if (MODE == 2) {
            // concat channels 0..63: broadcast feat1 over K, gn1 affine
            for (int idx = tid; idx < 128; idx += 256) {
                int cp2 = idx >> 2, g = idx & 3, ch = cp2 * 2;
                int n = ((colbase) >> 5) + g;
                float v0 = sc_feat1[(size_t)(b * 64 + ch) * N_ + n];
                float v1 = sc_feat1[(size_t)(b * 64 + ch + 1) * N_ + n];
                v0 = fmaf(v0, g_scale[0][b][ch],     g_shift[0][b][ch]);
                v1 = fmaf(v1, g_scale[0][b][ch + 1], g_shift[0][b][ch + 1]);
                uint32_t hi, lo;
                split2(v0, v1, hi, lo);
#pragma unroll
                for (int j = 0; j < 32; ++j) {
                    Bh[(g * 32 + j) * LDB + cp2] = hi;
                    Bl[(g * 32 + j) * LDB + cp2] = lo;
                }
            }
        }
    };

    // ---- prologue ---------------------------------------------------------
    const int G = gridDim.x;
    int t0 = blockIdx.x;
    load_async(t0);
    CP_WAIT0();
    __syncthreads();
    convert(t0);
    __syncthreads();

    for (int t = t0; t < TILES; t += G) {
        const int tn = t + G;
        if (tn < TILES) load_async(tn);

        // ---- MMA: D(fp32) += Ah*Bh + Ah*Bl + Al*Bh -------------------------
        float D[2][NT][4];
#pragma unroll
        for (int mt = 0; mt < 2; ++mt)
#pragma unroll
            for (int nt = 0; nt < NT; ++nt)
#pragma unroll
                for (int e = 0; e < 4; ++e) D[mt][nt][e] = 0.f;

#pragma unroll
        for (int kk = 0; kk < 8; ++kk) {
            const int kc = kk * 8;
            uint32_t ah[2][4], al[2][4];
#pragma unroll
            for (int mt = 0; mt < 2; ++mt) {
                int r = wrow * 32 + mt * 16 + lq;
                int base = r * LDB + kc + lr;
                ah[mt][0] = Ah[base];
                ah[mt][1] = Ah[base + 8 * LDB];
                ah[mt][2] = Ah[base + 4];
                ah[mt][3] = Ah[base + 8 * LDB + 4];
                al[mt][0] = Al[base];
                al[mt][1] = Al[base + 8 * LDB];
                al[mt][2] = Al[base + 4];
                al[mt][3] = Al[base + 8 * LDB + 4];
            }
#pragma unroll
            for (int nt = 0; nt < NT; ++nt) {
                int n = wcol * CW + nt * 8 + lq;
                int nb = n * LDB + kc + lr;
                uint32_t bh0 = Bh[nb], bh1 = Bh[nb + 4];
                uint32_t bl0 = Bl[nb], bl1 = Bl[nb + 4];
#pragma unroll
                for (int mt = 0; mt < 2; ++mt) {
                    MMA_BF16(D[mt][nt], ah[mt][0], ah[mt][1], ah[mt][2], ah[mt][3], bh0, bh1);
                    MMA_BF16(D[mt][nt], ah[mt][0], ah[mt][1], ah[mt][2], ah[mt][3], bl0, bl1);
                    MMA_BF16(D[mt][nt], al[mt][0], al[mt][1], al[mt][2], al[mt][3], bh0, bh1);
                }
            }
        }

        // ---- epilogue from register fragments ------------------------------
        const int b = t >> 10, colbase = (t & 1023) << 7;
        if (MODE != 3) {
            constexpr int SLOT  = (MODE == 0) ? 0 : ((MODE == 2) ? 1 : 2);
            constexpr int CHOFF = (MODE == 0) ? 64 : 0;
            float* dst = (MODE == 0) ? sc_g1 : ((MODE == 1) ? sc_y3 : sc_x1);
#pragma unroll
            for (int mt = 0; mt < 2; ++mt) {
#pragma unroll
                for (int half = 0; half < 2; ++half) {
                    int r = wrow * 32 + mt * 16 + lq + half * 8;
                    float bias = __ldg(p.bias + r);
                    float s = 0.f, q = 0.f;
                    float* drow = dst + ((size_t)(b * O + r)) * CPB + colbase + wcol * CW;
#pragma unroll
                    for (int nt = 0; nt < NT; ++nt) {
                        float v0 = D[mt][nt][half * 2 + 0] + bias;
                        float v1 = D[mt][nt][half * 2 + 1] + bias;
                        if (MODE != 1) { v0 = fmaxf(v0, 0.f); v1 = fmaxf(v1, 0.f); }
                        *(float2*)(drow + nt * 8 + lr * 2) = make_float2(v0, v1);
                        s += v0 + v1;
                        q += v0 * v0 + v1 * v1;
                    }
                    s += __shfl_xor_sync(0xffffffffu, s, 1);
                    s += __shfl_xor_sync(0xffffffffu, s, 2);
                    q += __shfl_xor_sync(0xffffffffu, q, 1);
                    q += __shfl_xor_sync(0xffffffffu, q, 2);
                    if (lr == 0) {
                        atomicAdd(&g_sum[SLOT][b][CHOFF + r], (double)s);
                        atomicAdd(&g_sq [SLOT][b][CHOFF + r], (double)q);
                    }
                }
            }
        } else {
#pragma unroll
            for (int mt = 0; mt < 2; ++mt) {
#pragma unroll
                for (int half = 0; half < 2; ++half) {
                    int c = wrow * 32 + mt * 16 + lq + half * 8;
                    float sc3 = g_scale[2][b][c], sh3 = g_shift[2][b][c];
#pragma unroll
                    for (int ng = 0; ng < 2; ++ng) {
                        int ncb = colbase + wcol * CW + ng * 32;
                        int n = ncb >> 5;
                        int cnt = __ldg(p.count + b * N_ + n);
                        if (cnt < 1) cnt = 1;
                        float v[8];
                        float mx = -3.0e38f;
#pragma unroll
                        for (int tt = 0; tt < 4; ++tt) {
#pragma unroll
                            for (int e = 0; e < 2; ++e) {
                                int k = tt * 8 + lr * 2 + e;
                                float x = D[mt][ng * 4 + tt][half * 2 + e];
                                x = (k < cnt) ? x : -1e9f;
                                v[tt * 2 + e] = x;
                                mx = fmaxf(mx, x);
                            }
                        }
                        mx = fmaxf(mx, __shfl_xor_sync(0xffffffffu, mx, 1));
                        mx = fmaxf(mx, __shfl_xor_sync(0xffffffffu, mx, 2));
                        const float* yrow = sc_y3 + ((size_t)(b * 128 + c) * N_ + n) * K_;
                        float num = 0.f, den = 0.f;
#pragma unroll
                        for (int tt = 0; tt < 4; ++tt) {
                            float2 y = *(const float2*)(yrow + tt * 8 + lr * 2);
                            float e0 = __expf(v[tt * 2 + 0] - mx);
                            float e1 = __expf(v[tt * 2 + 1] - mx);
                            float g0 = fmaxf(fmaf(sc3, y.x, sh3), 0.f);
                            float g1 = fmaxf(fmaf(sc3, y.y, sh3), 0.f);
                            num += e0 * g0 + e1 * g1;
                            den += e0 + e1;
                        }
                        num += __shfl_xor_sync(0xffffffffu, num, 1);
                        num += __shfl_xor_sync(0xffffffffu, num, 2);
                        den += __shfl_xor_sync(0xffffffffu, den, 1);
                        den += __shfl_xor_sync(0xffffffffu, den, 2);
                        if (lr == 0)
                            p.out[(size_t)(b * 128 + c) * N_ + n] = num / den;
                    }
                }
            }
        }

        if (tn < TILES) {
            CP_WAIT0();
            __syncthreads();
            convert(tn);
            __syncthreads();
        }
    }
}

// ---------------------------------------------------------------------------
__global__ void finalize_k(int slot, const float* __restrict__ wgn,
                           const float* __restrict__ bgn) {
    int t = threadIdx.x;
    int b = t >> 7, c = t & 127;
    int g = (c >> 2) << 2;
    double s = g_sum[slot][b][g] + g_sum[slot][b][g + 1] +
               g_sum[slot][b][g + 2] + g_sum[slot][b][g + 3];
    double q = g_sq[slot][b][g] + g_sq[slot][b][g + 1] +
               g_sq[slot][b][g + 2] + g_sq[slot][b][g + 3];
    const double cnte = 4.0 * N_ * K_;
    double mu  = s / cnte;
    double var = q / cnte - mu * mu;
    float rstd = (float)(1.0 / sqrt(var + 1e-5));
    float sc   = wgn[c] * rstd;
    g_scale[slot][b][c] = sc;
    g_shift[slot][b][c] = bgn[c] - (float)mu * sc;
}

// ---------------------------------------------------------------------------
extern "C" void kernel_launch(void* const* d_in, const int* in_sizes, int n_in,
                              void* d_out, int out_size) {
    const float* feat   = (const float*)d_in[0];
    const float* gf     = (const float*)d_in[1];
    const float* gfo    = (const float*)d_in[2];
    const int*   count  = (const int*)  d_in[3];
    const float* W_feat = (const float*)d_in[4];
    const float* b_feat = (const float*)d_in[5];
    const float* W_grp  = (const float*)d_in[6];
    const float* b_grp  = (const float*)d_in[7];
    const float* gn1_w  = (const float*)d_in[8];
    const float* gn1_b  = (const float*)d_in[9];
    const float* W_wc1  = (const float*)d_in[10];
    const float* b_wc1  = (const float*)d_in[11];
    const float* gn2_w  = (const float*)d_in[12];
    const float* gn2_b  = (const float*)d_in[13];
    const float* W_wc2  = (const float*)d_in[14];
    const float* b_wc2  = (const float*)d_in[15];
    const float* W_fo   = (const float*)d_in[16];
    const float* b_fo   = (const float*)d_in[17];
    const float* gn3_w  = (const float*)d_in[18];
    const float* gn3_b  = (const float*)d_in[19];
    float* out = (float*)d_out;

    constexpr int LDB = 68;
    const int smem0 = (2 * 64 * LDB + 2 * 128 * LDB) * 4 + 128 * 128 * 4;   // 169984
    const int smem1 = (2 * 128 * LDB + 2 * 128 * LDB) * 4 + 128 * 128 * 4;  // 204800
    const int smem2 = (2 * 128 * LDB + 2 * 128 * LDB) * 4 + 64 * 128 * 4;   // 172032
    cudaFuncSetAttribute(hmma_k<0>, cudaFuncAttributeMaxDynamicSharedMemorySize, smem0);
    cudaFuncSetAttribute(hmma_k<1>, cudaFuncAttributeMaxDynamicSharedMemorySize, smem1);
    cudaFuncSetAttribute(hmma_k<2>, cudaFuncAttributeMaxDynamicSharedMemorySize, smem2);
    cudaFuncSetAttribute(hmma_k<3>, cudaFuncAttributeMaxDynamicSharedMemorySize, smem1);

    const int GRID = 148;

    zero_stats_k<<<2, 1024>>>();
    feat1_k<<<dim3(N_ / 32, B_), 256>>>(feat, W_feat, b_feat);

    { Ptrs p{gf,  W_grp, b_grp, nullptr, nullptr};
      hmma_k<0><<<GRID, 256, smem0>>>(p); }      // g1 + gn1 stats (ch 64+)
    { Ptrs p{gfo, W_fo,  b_fo,  nullptr, nullptr};
      hmma_k<1><<<GRID, 256, smem1>>>(p); }      // y3 + gn3 stats

    finalize_k<<<1, 512>>>(0, gn1_w, gn1_b);
    finalize_k<<<1, 512>>>(2, gn3_w, gn3_b);

    { Ptrs p{nullptr, W_wc1, b_wc1, nullptr, nullptr};
      hmma_k<2><<<GRID, 256, smem2>>>(p); }      // x1 + gn2 stats

    finalize_k<<<1, 512>>>(1, gn2_w, gn2_b);

    { Ptrs p{nullptr, W_wc2, b_wc2, count, out};
      hmma_k<3><<<GRID, 256, smem1>>>(p); }      // scores -> softmax -> out
}

// round 4
// speedup vs baseline: 3.2430x; 1.0882x over previous
#include <cuda_runtime.h>
#include <cuda_bf16.h>
#include <cstdint>
#include <cstddef>

// ---------------------------------------------------------------------------
constexpr int B_ = 4;
constexpr int N_ = 4096;
constexpr int K_ = 32;
constexpr int CPB = N_ * K_;              // 131072 columns per batch
constexpr int TILES = B_ * (CPB / 128);   // 4096 tiles of 128 columns
constexpr int LDB = 68;                   // u32 per row of bf16x2 tiles (pad 4)
constexpr int SP  = 130;                  // stage row stride in floats

// ---------------------------------------------------------------------------
// Scratch
// ---------------------------------------------------------------------------
__device__ float sc_feat1[(size_t)B_ * 64 * N_];
__device__ float sc_g1  [(size_t)B_ * 64 * CPB];
__device__ float sc_y3  [(size_t)B_ * 128 * CPB];
__device__ float sc_x1  [(size_t)B_ * 128 * CPB];

__device__ double g_sum  [3][B_][128];
__device__ double g_sq   [3][B_][128];
__device__ float  g_scale[3][B_][128];
__device__ float  g_shift[3][B_][128];

// ---------------------------------------------------------------------------
__device__ __forceinline__ uint32_t smem_to_u32(const void* p) {
    uint32_t a;
    asm("{ .reg .u64 t; cvta.to.shared.u64 t, %1; cvt.u32.u64 %0, t; }"
        : "=r"(a) : "l"(p));
    return a;
}
__device__ __forceinline__ void cp_async8(uint32_t dst, const void* src) {
    asm volatile("cp.async.ca.shared.global [%0], [%1], 8;" :: "r"(dst), "l"(src));
}
#define CP_COMMIT() asm volatile("cp.async.commit_group;" ::: "memory")
#define CP_WAIT0()  asm volatile("cp.async.wait_group 0;" ::: "memory")

#define MMA_BF16(d, a0, a1, a2, a3, b0, b1) \
    asm volatile("mma.sync.aligned.m16n8k16.row.col.f32.bf16.bf16.f32 " \
        "{%0,%1,%2,%3},{%4,%5,%6,%7},{%8,%9},{%0,%1,%2,%3};" \
        : "+f"((d)[0]), "+f"((d)[1]), "+f"((d)[2]), "+f"((d)[3]) \
        : "r"(a0), "r"(a1), "r"(a2), "r"(a3), "r"(b0), "r"(b1))

// bf16 2-way split of a float pair -> packed bf16x2 hi and lo
__device__ __forceinline__ void split2(float x0, float x1, uint32_t& hi, uint32_t& lo) {
    __nv_bfloat162 h = __float22bfloat162_rn(make_float2(x0, x1));
    float r0 = x0 - __bfloat162float(h.x);
    float r1 = x1 - __bfloat162float(h.y);
    __nv_bfloat162 l = __float22bfloat162_rn(make_float2(r0, r1));
    hi = *(uint32_t*)&h;
    lo = *(uint32_t*)&l;
}

// ---------------------------------------------------------------------------
__global__ void zero_stats_k() {
    int t = blockIdx.x * blockDim.x + threadIdx.x;
    if (t < 3 * B_ * 128) {
        (&g_sum[0][0][0])[t] = 0.0;
        (&g_sq [0][0][0])[t] = 0.0;
    }
}

// ---------------------------------------------------------------------------
__global__ void __launch_bounds__(256) feat1_k(const float* __restrict__ feat,
                                               const float* __restrict__ Wf,
                                               const float* __restrict__ bf) {
    __shared__ float Ws[64 * 128];
    __shared__ float Fs[128 * 32];
    const int b  = blockIdx.y;
    const int n0 = blockIdx.x * 32;
    const int tid = threadIdx.x;

    for (int idx = tid; idx < 64 * 128; idx += 256) Ws[idx] = Wf[idx];
    for (int idx = tid; idx < 128 * 32; idx += 256) {
        int c = idx >> 5, jj = idx & 31;
        Fs[idx] = feat[(size_t)(b * 128 + c) * N_ + n0 + jj];
    }
    __syncthreads();

    const int jj = tid & 31;
    const int w  = tid >> 5;
    float acc[8];
#pragma unroll
    for (int oi = 0; oi < 8; ++oi) acc[oi] = __ldg(bf + w * 8 + oi);
#pragma unroll 4
    for (int c = 0; c < 128; ++c) {
        float x = Fs[c * 32 + jj];
#pragma unroll
        for (int oi = 0; oi < 8; ++oi)
            acc[oi] = fmaf(Ws[(w * 8 + oi) * 128 + c], x, acc[oi]);
    }
#pragma unroll
    for (int oi = 0; oi < 8; ++oi) {
        int o = w * 8 + oi;
        float v = fmaxf(acc[oi], 0.f);
        sc_feat1[(size_t)(b * 64 + o) * N_ + n0 + jj] = v;
        float s = v, q = v * v;
#pragma unroll
        for (int off = 16; off; off >>= 1) {
            s += __shfl_xor_sync(0xffffffffu, s, off);
            q += __shfl_xor_sync(0xffffffffu, q, off);
        }
        if (jj == 0) {
            atomicAdd(&g_sum[0][b][o], (double)(32.0f * s));
            atomicAdd(&g_sq [0][b][o], (double)(32.0f * q));
        }
    }
}

// ---------------------------------------------------------------------------
// HMMA GEMM stages; 512 threads, persistent CTAs, conflict-free convert.
// ---------------------------------------------------------------------------
struct Ptrs {
    const float* X;
    const float* W;
    const float* bias;
    const int*   count;
    float*       out;
};

template <int MODE>
__global__ void __launch_bounds__(512, 1) hmma_k(Ptrs p) {
    constexpr int O   = (MODE == 0) ? 64 : 128;
    constexpr int WR  = (MODE == 0) ? 2 : 4;       // warp rows
    constexpr int WC  = 16 / WR;                   // warp cols (8 or 4)
    constexpr int CW  = 128 / WC;                  // cols per warp (16 or 32)
    constexpr int NT  = CW / 8;                    // n8 tiles per warp (2 or 4)
    constexpr int CH  = (MODE == 2) ? 64 : 128;    // staged channels

    extern __shared__ char smem[];
    uint32_t* Ah = (uint32_t*)smem;            // [O][LDB]
    uint32_t* Al = Ah + O * LDB;
    uint32_t* Bh = Al + O * LDB;               // [128 n-cols][LDB]
    uint32_t* Bl = Bh + 128 * LDB;
    float* stage = (float*)(Bl + 128 * LDB);   // [CH][SP] fp32
    const uint32_t stage_u = smem_to_u32(stage);

    const int tid = threadIdx.x;
    const int wid = tid >> 5, lane = tid & 31;
    const int wrow = wid / WC, wcol = wid % WC;
    const int lq = lane >> 2, lr = lane & 3;
    const int la = lane >> 2, lb = lane & 3;   // convert mapping: col-offset, k-offset

    const float* src = (MODE == 0 || MODE == 1) ? p.X : ((MODE == 2) ? sc_g1 : sc_x1);

    // ---- convert weights once ---------------------------------------------
    for (int idx = tid; idx < O * 32; idx += 512) {
        int r = idx >> 5, c4 = (idx & 31) * 4;
        float4 w = *(const float4*)(p.W + r * 128 + c4);
        uint32_t h0, l0, h1, l1;
        split2(w.x, w.y, h0, l0);
        split2(w.z, w.w, h1, l1);
        Ah[r * LDB + c4 / 2] = h0; Ah[r * LDB + c4 / 2 + 1] = h1;
        Al[r * LDB + c4 / 2] = l0; Al[r * LDB + c4 / 2 + 1] = l1;
    }

    auto load_async = [&](int t) {
        int b = t >> 10, colbase = (t & 1023) << 7;
        for (int idx = tid; idx < CH * 64; idx += 512) {
            int ch = idx >> 6, c2 = (idx & 63) * 2;
            const float* s = src + ((size_t)(b * CH + ch)) * CPB + colbase + c2;
            cp_async8(stage_u + (uint32_t)(ch * SP + c2) * 4u, s);
        }
        CP_COMMIT();
    };

    // convert: lanes sweep k (STS bank = 4*col + k -> conflict-free),
    // stage stride 130 makes the transposed reads conflict-free too.
    auto convert = [&](int t) {
        int b = t >> 10, colbase = (t & 1023) << 7;
        const int col = wid * 8 + la;
        if (MODE != 2) {
#pragma unroll
            for (int j = 0; j < 16; ++j) {
                int k = lb + 4 * j;            // u32 k-index 0..63
                int ch = 2 * k;
                float x0 = stage[ch * SP + col];
                float x1 = stage[(ch + 1) * SP + col];
                if (MODE == 3) {
                    x0 = fmaf(x0, g_scale[1][b][ch],     g_shift[1][b][ch]);
                    x1 = fmaf(x1, g_scale[1][b][ch + 1], g_shift[1][b][ch + 1]);
                }
                uint32_t hi, lo;
                split2(x0, x1, hi, lo);
                Bh[col * LDB + k] = hi;
                Bl[col * LDB + k] = lo;
            }
        } else {
            // g1 channels (64..127) -> k 32..63
#pragma unroll
            for (int j = 0; j < 8; ++j) {
                int k32 = lb + 4 * j;          // 0..31
                int ch = 2 * k32;              // g1 local channel
                int cc = 64 + ch;
                float x0 = stage[ch * SP + col];
                float x1 = stage[(ch + 1) * SP + col];
                x0 = fmaf(x0, g_scale[0][b][cc],     g_shift[0][b][cc]);
                x1 = fmaf(x1, g_scale[0][b][cc + 1], g_shift[0][b][cc + 1]);
                uint32_t hi, lo;
                split2(x0, x1, hi, lo);
                Bh[col * LDB + 32 + k32] = hi;
                Bl[col * LDB + 32 + k32] = lo;
            }
            // feat1 channels (0..63) -> k 0..31 (broadcast over K within n)
            int n = (colbase >> 5) + (col >> 5);
#pragma unroll
            for (int j = 0; j < 8; ++j) {
                int kf = lb + 4 * j;           // 0..31
                int ch = 2 * kf;
                float v0 = __ldg(sc_feat1 + (size_t)(b * 64 + ch) * N_ + n);
                float v1 = __ldg(sc_feat1 + (size_t)(b * 64 + ch + 1) * N_ + n);
                v0 = fmaf(v0, g_scale[0][b][ch],     g_shift[0][b][ch]);
                v1 = fmaf(v1, g_scale[0][b][ch + 1], g_shift[0][b][ch + 1]);
                uint32_t hi, lo;
                split2(v0, v1, hi, lo);
                Bh[col * LDB + kf] = hi;
                Bl[col * LDB + kf] = lo;
            }
        }
    };

    // ---- prologue -----------------------------------------------------------
    const int G = gridDim.x;
    int t0 = blockIdx.x;
    if (t0 < TILES) load_async(t0);
    CP_WAIT0();
    __syncthreads();
    if (t0 < TILES) convert(t0);
    __syncthreads();

    for (int t = t0; t < TILES; t += G) {
        const int tn = t + G;
        if (tn < TILES) load_async(tn);

        // ---- MMA: D += Ah*Bh + Ah*Bl + Al*Bh --------------------------------
        float D[2][NT][4];
#pragma unroll
        for (int mt = 0; mt < 2; ++mt)
#pragma unroll
            for (int nt = 0; nt < NT; ++nt)
#pragma unroll
                for (int e = 0; e < 4; ++e) D[mt][nt][e] = 0.f;

#pragma unroll
        for (int kk = 0; kk < 8; ++kk) {
            const int kc = kk * 8;
            uint32_t ah[2][4], al[2][4];
#pragma unroll
            for (int mt = 0; mt < 2; ++mt) {
                int r = wrow * 32 + mt * 16 + lq;
                int base = r * LDB + kc + lr;
                ah[mt][0] = Ah[base];
                ah[mt][1] = Ah[base + 8 * LDB];
                ah[mt][2] = Ah[base + 4];
                ah[mt][3] = Ah[base + 8 * LDB + 4];
                al[mt][0] = Al[base];
                al[mt][1] = Al[base + 8 * LDB];
                al[mt][2] = Al[base + 4];
                al[mt][3] = Al[base + 8 * LDB + 4];
            }
#pragma unroll
            for (int nt = 0; nt < NT; ++nt) {
                int n = wcol * CW + nt * 8 + lq;
                int nb = n * LDB + kc + lr;
                uint32_t bh0 = Bh[nb], bh1 = Bh[nb + 4];
                uint32_t bl0 = Bl[nb], bl1 = Bl[nb + 4];
#pragma unroll
                for (int mt = 0; mt < 2; ++mt) {
                    MMA_BF16(D[mt][nt], ah[mt][0], ah[mt][1], ah[mt][2], ah[mt][3], bh0, bh1);
                    MMA_BF16(D[mt][nt], ah[mt][0], ah[mt][1], ah[mt][2], ah[mt][3], bl0, bl1);
                    MMA_BF16(D[mt][nt], al[mt][0], al[mt][1], al[mt][2], al[mt][3], bh0, bh1);
                }
            }
        }

        // ---- epilogue from register fragments --------------------------------
        const int b = t >> 10, colbase = (t & 1023) << 7;
        if (MODE != 3) {
            constexpr int SLOT  = (MODE == 0) ? 0 : ((MODE == 2) ? 1 : 2);
            constexpr int CHOFF = (MODE == 0) ? 64 : 0;
            float* dst = (MODE == 0) ? sc_g1 : ((MODE == 1) ? sc_y3 : sc_x1);
#pragma unroll
            for (int mt = 0; mt < 2; ++mt) {
#pragma unroll
                for (int half = 0; half < 2; ++half) {
                    int r = wrow * 32 + mt * 16 + lq + half * 8;
                    float bias = __ldg(p.bias + r);
                    float s = 0.f, q = 0.f;
                    float* drow = dst + ((size_t)(b * O + r)) * CPB + colbase + wcol * CW;
#pragma unroll
                    for (int nt = 0; nt < NT; ++nt) {
                        float v0 = D[mt][nt][half * 2 + 0] + bias;
                        float v1 = D[mt][nt][half * 2 + 1] + bias;
                        if (MODE != 1) { v0 = fmaxf(v0, 0.f); v1 = fmaxf(v1, 0.f); }
                        *(float2*)(drow + nt * 8 + lr * 2) = make_float2(v0, v1);
                        s += v0 + v1;
                        q += v0 * v0 + v1 * v1;
                    }
                    s += __shfl_xor_sync(0xffffffffu, s, 1);
                    s += __shfl_xor_sync(0xffffffffu, s, 2);
                    q += __shfl_xor_sync(0xffffffffu, q, 1);
                    q += __shfl_xor_sync(0xffffffffu, q, 2);
                    if (lr == 0) {
                        atomicAdd(&g_sum[SLOT][b][CHOFF + r], (double)s);
                        atomicAdd(&g_sq [SLOT][b][CHOFF + r], (double)q);
                    }
                }
            }
        } else {
            // one n per warp column (CW == 32)
            int n = (colbase >> 5) + wcol;
            int cnt = __ldg(p.count + b * N_ + n);
            if (cnt < 1) cnt = 1;
#pragma unroll
            for (int mt = 0; mt < 2; ++mt) {
#pragma unroll
                for (int half = 0; half < 2; ++half) {
                    int c = wrow * 32 + mt * 16 + lq + half * 8;
                    float sc3 = g_scale[2][b][c], sh3 = g_shift[2][b][c];
                    float v[8];
                    float mx = -3.0e38f;
#pragma unroll
                    for (int nt = 0; nt < 4; ++nt) {
#pragma unroll
                        for (int e = 0; e < 2; ++e) {
                            int k = nt * 8 + lr * 2 + e;
                            float x = D[mt][nt][half * 2 + e];
                            x = (k < cnt) ? x : -1e9f;
                            v[nt * 2 + e] = x;
                            mx = fmaxf(mx, x);
                        }
                    }
                    mx = fmaxf(mx, __shfl_xor_sync(0xffffffffu, mx, 1));
                    mx = fmaxf(mx, __shfl_xor_sync(0xffffffffu, mx, 2));
                    const float* yrow = sc_y3 + ((size_t)(b * 128 + c) * N_ + n) * K_;
                    float num = 0.f, den = 0.f;
#pragma unroll
                    for (int nt = 0; nt < 4; ++nt) {
                        float2 y = *(const float2*)(yrow + nt * 8 + lr * 2);
                        float e0 = __expf(v[nt * 2 + 0] - mx);
                        float e1 = __expf(v[nt * 2 + 1] - mx);
                        float g0 = fmaxf(fmaf(sc3, y.x, sh3), 0.f);
                        float g1 = fmaxf(fmaf(sc3, y.y, sh3), 0.f);
                        num += e0 * g0 + e1 * g1;
                        den += e0 + e1;
                    }
                    num += __shfl_xor_sync(0xffffffffu, num, 1);
                    num += __shfl_xor_sync(0xffffffffu, num, 2);
                    den += __shfl_xor_sync(0xffffffffu, den, 1);
                    den += __shfl_xor_sync(0xffffffffu, den, 2);
                    if (lr == 0)
                        p.out[(size_t)(b * 128 + c) * N_ + n] = num / den;
                }
            }
        }

        if (tn < TILES) {
            CP_WAIT0();
            __syncthreads();
            convert(tn);
            __syncthreads();
        }
    }
}

// ---------------------------------------------------------------------------
__global__ void finalize_k(int slot, const float* __restrict__ wgn,
                           const float* __restrict__ bgn) {
    int t = threadIdx.x;
    int b = t >> 7, c = t & 127;
    int g = (c >> 2) << 2;
    double s = g_sum[slot][b][g] + g_sum[slot][b][g + 1] +
               g_sum[slot][b][g + 2] + g_sum[slot][b][g + 3];
    double q = g_sq[slot][b][g] + g_sq[slot][b][g + 1] +
               g_sq[slot][b][g + 2] + g_sq[slot][b][g + 3];
    const double cnte = 4.0 * N_ * K_;
    double mu  = s / cnte;
    double var = q / cnte - mu * mu;
    float rstd = (float)(1.0 / sqrt(var + 1e-5));
    float sc   = wgn[c] * rstd;
    g_scale[slot][b][c] = sc;
    g_shift[slot][b][c] = bgn[c] - (float)mu * sc;
}

// ---------------------------------------------------------------------------
extern "C" void kernel_launch(void* const* d_in, const int* in_sizes, int n_in,
                              void* d_out, int out_size) {
    const float* feat   = (const float*)d_in[0];
    const float* gf     = (const float*)d_in[1];
    const float* gfo    = (const float*)d_in[2];
    const int*   count  = (const int*)  d_in[3];
    const float* W_feat = (const float*)d_in[4];
    const float* b_feat = (const float*)d_in[5];
    const float* W_grp  = (const float*)d_in[6];
    const float* b_grp  = (const float*)d_in[7];
    const float* gn1_w  = (const float*)d_in[8];
    const float* gn1_b  = (const float*)d_in[9];
    const float* W_wc1  = (const float*)d_in[10];
    const float* b_wc1  = (const float*)d_in[11];
    const float* gn2_w  = (const float*)d_in[12];
    const float* gn2_b  = (const float*)d_in[13];
    const float* W_wc2  = (const float*)d_in[14];
    const float* b_wc2  = (const float*)d_in[15];
    const float* W_fo   = (const float*)d_in[16];
    const float* b_fo   = (const float*)d_in[17];
    const float* gn3_w  = (const float*)d_in[18];
    const float* gn3_b  = (const float*)d_in[19];
    float* out = (float*)d_out;

    const int smem0 = (2 * 64 * LDB + 2 * 128 * LDB) * 4 + 128 * SP * 4;   // 171008
    const int smem1 = (2 * 128 * LDB + 2 * 128 * LDB) * 4 + 128 * SP * 4;  // 205824
    const int smem2 = (2 * 128 * LDB + 2 * 128 * LDB) * 4 + 64 * SP * 4;   // 172544
    cudaFuncSetAttribute(hmma_k<0>, cudaFuncAttributeMaxDynamicSharedMemorySize, smem0);
    cudaFuncSetAttribute(hmma_k<1>, cudaFuncAttributeMaxDynamicSharedMemorySize, smem1);
    cudaFuncSetAttribute(hmma_k<2>, cudaFuncAttributeMaxDynamicSharedMemorySize, smem2);
    cudaFuncSetAttribute(hmma_k<3>, cudaFuncAttributeMaxDynamicSharedMemorySize, smem1);

    const int GRID = 148;

    zero_stats_k<<<2, 1024>>>();
    feat1_k<<<dim3(N_ / 32, B_), 256>>>(feat, W_feat, b_feat);

    { Ptrs p{gf,  W_grp, b_grp, nullptr, nullptr};
      hmma_k<0><<<GRID, 512, smem0>>>(p); }      // g1 + gn1 stats (ch 64+)
    { Ptrs p{gfo, W_fo,  b_fo,  nullptr, nullptr};
      hmma_k<1><<<GRID, 512, smem1>>>(p); }      // y3 + gn3 stats

    finalize_k<<<1, 512>>>(0, gn1_w, gn1_b);
    finalize_k<<<1, 512>>>(2, gn3_w, gn3_b);

    { Ptrs p{nullptr, W_wc1, b_wc1, nullptr, nullptr};
      hmma_k<2><<<GRID, 512, smem2>>>(p); }      // x1 + gn2 stats

    finalize_k<<<1, 512>>>(1, gn2_w, gn2_b);

    { Ptrs p{nullptr, W_wc2, b_wc2, count, out};
      hmma_k<3><<<GRID, 512, smem1>>>(p); }      // scores -> softmax -> out
}

// round 5
// speedup vs baseline: 4.9637x; 1.5306x over previous
#include <cuda_runtime.h>
#include <cuda_fp16.h>
#include <cstdint>
#include <cstddef>

// ---------------------------------------------------------------------------
constexpr int B_ = 4;
constexpr int N_ = 4096;
constexpr int K_ = 32;
constexpr int CPB = N_ * K_;              // 131072 columns per batch
constexpr int TILES = B_ * (CPB / 128);   // 4096 tiles of 128 columns
constexpr int LDB = 68;                   // u32 stride per n-col of B tile
constexpr int SP  = 132;                  // stage row stride (floats), 16B aligned

// ---------------------------------------------------------------------------
// Scratch
// ---------------------------------------------------------------------------
__device__ float sc_feat1[(size_t)B_ * 64 * N_];
__device__ float sc_g1  [(size_t)B_ * 64 * CPB];
__device__ float sc_y3  [(size_t)B_ * 128 * CPB];
__device__ float sc_x1  [(size_t)B_ * 128 * CPB];

__device__ double g_sum  [3][B_][128];
__device__ double g_sq   [3][B_][128];
__device__ float  g_scale[3][B_][128];
__device__ float  g_shift[3][B_][128];

// ---------------------------------------------------------------------------
__device__ __forceinline__ uint32_t smem_to_u32(const void* p) {
    uint32_t a;
    asm("{ .reg .u64 t; cvta.to.shared.u64 t, %1; cvt.u32.u64 %0, t; }"
        : "=r"(a) : "l"(p));
    return a;
}
__device__ __forceinline__ void cp_async16(uint32_t dst, const void* src) {
    asm volatile("cp.async.cg.shared.global [%0], [%1], 16;" :: "r"(dst), "l"(src));
}
#define CP_COMMIT() asm volatile("cp.async.commit_group;" ::: "memory")
#define CP_WAIT0()  asm volatile("cp.async.wait_group 0;" ::: "memory")

#define MMA_F16(d, a0, a1, a2, a3, b0, b1) \
    asm volatile("mma.sync.aligned.m16n8k16.row.col.f32.f16.f16.f32 " \
        "{%0,%1,%2,%3},{%4,%5,%6,%7},{%8,%9},{%0,%1,%2,%3};" \
        : "+f"((d)[0]), "+f"((d)[1]), "+f"((d)[2]), "+f"((d)[3]) \
        : "r"(a0), "r"(a1), "r"(a2), "r"(a3), "r"(b0), "r"(b1))

// fp16 pack (single) of a float pair
__device__ __forceinline__ uint32_t packh(float x0, float x1) {
    __half2 h = __float22half2_rn(make_float2(x0, x1));
    return *(uint32_t*)&h;
}
// fp16 2-way split of a float pair
__device__ __forceinline__ void splith(float x0, float x1, uint32_t& hi, uint32_t& lo) {
    __half2 h = __float22half2_rn(make_float2(x0, x1));
    float2 hf = __half22float2(h);
    __half2 l = __float22half2_rn(make_float2(x0 - hf.x, x1 - hf.y));
    hi = *(uint32_t*)&h;
    lo = *(uint32_t*)&l;
}

// ---------------------------------------------------------------------------
__global__ void zero_stats_k() {
    int t = blockIdx.x * blockDim.x + threadIdx.x;
    if (t < 3 * B_ * 128) {
        (&g_sum[0][0][0])[t] = 0.0;
        (&g_sq [0][0][0])[t] = 0.0;
    }
}

// ---------------------------------------------------------------------------
__global__ void __launch_bounds__(256) feat1_k(const float* __restrict__ feat,
                                               const float* __restrict__ Wf,
                                               const float* __restrict__ bf) {
    __shared__ float Ws[64 * 128];
    __shared__ float Fs[128 * 32];
    const int b  = blockIdx.y;
    const int n0 = blockIdx.x * 32;
    const int tid = threadIdx.x;

    for (int idx = tid; idx < 64 * 128; idx += 256) Ws[idx] = Wf[idx];
    for (int idx = tid; idx < 128 * 32; idx += 256) {
        int c = idx >> 5, jj = idx & 31;
        Fs[idx] = feat[(size_t)(b * 128 + c) * N_ + n0 + jj];
    }
    __syncthreads();

    const int jj = tid & 31;
    const int w  = tid >> 5;
    float acc[8];
#pragma unroll
    for (int oi = 0; oi < 8; ++oi) acc[oi] = __ldg(bf + w * 8 + oi);
#pragma unroll 4
    for (int c = 0; c < 128; ++c) {
        float x = Fs[c * 32 + jj];
#pragma unroll
        for (int oi = 0; oi < 8; ++oi)
            acc[oi] = fmaf(Ws[(w * 8 + oi) * 128 + c], x, acc[oi]);
    }
#pragma unroll
    for (int oi = 0; oi < 8; ++oi) {
        int o = w * 8 + oi;
        float v = fmaxf(acc[oi], 0.f);
        sc_feat1[(size_t)(b * 64 + o) * N_ + n0 + jj] = v;
        float s = v, q = v * v;
#pragma unroll
        for (int off = 16; off; off >>= 1) {
            s += __shfl_xor_sync(0xffffffffu, s, off);
            q += __shfl_xor_sync(0xffffffffu, q, off);
        }
        if (jj == 0) {
            atomicAdd(&g_sum[0][b][o], (double)(32.0f * s));
            atomicAdd(&g_sq [0][b][o], (double)(32.0f * q));
        }
    }
}

// ---------------------------------------------------------------------------
// HMMA stages: A (weights, fp16 hi+lo split) resident in registers,
// B single fp16, 2 MMAs per k16 step. 512 threads, persistent CTAs.
// ---------------------------------------------------------------------------
struct Ptrs {
    const float* X;
    const float* W;
    const float* bias;
    const int*   count;
    float*       out;
};

template <int MODE>
__global__ void __launch_bounds__(512, 1) hmma_k(Ptrs p) {
    constexpr int O   = (MODE == 0) ? 64 : 128;
    constexpr int NT  = (MODE == 0) ? 4 : 8;       // n8 tiles per warp
    constexpr int CW  = NT * 8;                    // cols per warp
    constexpr int CH  = (MODE == 2) ? 64 : 128;    // staged input channels

    extern __shared__ char smem[];
    uint32_t* Bh = (uint32_t*)smem;            // [128 n-cols][LDB]
    float* stage = (float*)(Bh + 128 * LDB);   // [CH][SP]
    const uint32_t stage_u = smem_to_u32(stage);

    const int tid  = threadIdx.x;
    const int wid  = tid >> 5, lane = tid & 31;
    const int lq   = lane >> 2, lr = lane & 3;
    const int wrow = (MODE == 0) ? (wid >> 2) : (wid >> 1);
    const int wcol = (MODE == 0) ? (wid & 3)  : (wid & 1);
    const int R0   = wrow * 16;
    const int C0   = wcol * CW;

    const float* src = (MODE == 0 || MODE == 1) ? p.X : ((MODE == 2) ? sc_g1 : sc_x1);

    // ---- A fragments (hi/lo fp16) resident in registers ---------------------
    uint32_t aH[8][4], aL[8][4];
#pragma unroll
    for (int kk = 0; kk < 8; ++kk) {
        int kb = kk * 16 + lr * 2;
        const float* w0 = p.W + (R0 + lq) * 128 + kb;
        const float* w1 = p.W + (R0 + lq + 8) * 128 + kb;
        float2 f0 = *(const float2*)(w0);
        float2 f1 = *(const float2*)(w1);
        float2 f2 = *(const float2*)(w0 + 8);
        float2 f3 = *(const float2*)(w1 + 8);
        splith(f0.x, f0.y, aH[kk][0], aL[kk][0]);
        splith(f1.x, f1.y, aH[kk][1], aL[kk][1]);
        splith(f2.x, f2.y, aH[kk][2], aL[kk][2]);
        splith(f3.x, f3.y, aH[kk][3], aL[kk][3]);
    }

    auto load_async = [&](int t) {
        int b = t >> 10, colbase = (t & 1023) << 7;
        for (int idx = tid; idx < CH * 32; idx += 512) {
            int ch = idx >> 5, c4 = (idx & 31) << 2;
            const float* s = src + ((size_t)(b * CH + ch)) * CPB + colbase + c4;
            cp_async16(stage_u + (uint32_t)(ch * SP + c4) * 4u, s);
        }
        CP_COMMIT();
    };

    // convert fp32 stage -> fp16 Bh; all smem access conflict-free
    auto convert = [&](int t) {
        int b = t >> 10, colbase = (t & 1023) << 7;
        const int col = wid * 8 + lq;
        if (MODE != 2) {
#pragma unroll
            for (int j = 0; j < 16; ++j) {
                int k = lr + 4 * j;            // u32 k-index 0..63
                int ch = 2 * k;
                float x0 = stage[ch * SP + col];
                float x1 = stage[ch * SP + SP + col];
                if (MODE == 3) {
                    x0 = fmaf(x0, g_scale[1][b][ch],     g_shift[1][b][ch]);
                    x1 = fmaf(x1, g_scale[1][b][ch + 1], g_shift[1][b][ch + 1]);
                }
                Bh[col * LDB + k] = packh(x0, x1);
            }
        } else {
            // g1 channels (64..127) -> k 32..63
#pragma unroll
            for (int j = 0; j < 8; ++j) {
                int k32 = lr + 4 * j;
                int ch = 2 * k32;
                int cc = 64 + ch;
                float x0 = stage[ch * SP + col];
                float x1 = stage[ch * SP + SP + col];
                x0 = fmaf(x0, g_scale[0][b][cc],     g_shift[0][b][cc]);
                x1 = fmaf(x1, g_scale[0][b][cc + 1], g_shift[0][b][cc + 1]);
                Bh[col * LDB + 32 + k32] = packh(x0, x1);
            }
            // feat1 channels (0..63) -> k 0..31 (broadcast over K within n)
            int n = (colbase >> 5) + (col >> 5);
#pragma unroll
            for (int j = 0; j < 8; ++j) {
                int kf = lr + 4 * j;
                int ch = 2 * kf;
                float v0 = __ldg(sc_feat1 + (size_t)(b * 64 + ch) * N_ + n);
                float v1 = __ldg(sc_feat1 + (size_t)(b * 64 + ch + 1) * N_ + n);
                v0 = fmaf(v0, g_scale[0][b][ch],     g_shift[0][b][ch]);
                v1 = fmaf(v1, g_scale[0][b][ch + 1], g_shift[0][b][ch + 1]);
                Bh[col * LDB + kf] = packh(v0, v1);
            }
        }
    };

    // ---- prologue -----------------------------------------------------------
    const int G = gridDim.x;
    int t0 = blockIdx.x;
    load_async(t0);
    CP_WAIT0();
    __syncthreads();
    convert(t0);
    __syncthreads();

    for (int t = t0; t < TILES; t += G) {
        const int tn = t + G;
        if (tn < TILES) load_async(tn);

        // ---- MMA: D += Ah*B + Al*B -----------------------------------------
        float D[NT][4];
#pragma unroll
        for (int nt = 0; nt < NT; ++nt)
#pragma unroll
            for (int e = 0; e < 4; ++e) D[nt][e] = 0.f;

#pragma unroll
        for (int kk = 0; kk < 8; ++kk) {
#pragma unroll
            for (int nt = 0; nt < NT; ++nt) {
                int n = C0 + nt * 8 + lq;
                uint32_t b0 = Bh[n * LDB + kk * 8 + lr];
                uint32_t b1 = Bh[n * LDB + kk * 8 + 4 + lr];
                MMA_F16(D[nt], aH[kk][0], aH[kk][1], aH[kk][2], aH[kk][3], b0, b1);
                MMA_F16(D[nt], aL[kk][0], aL[kk][1], aL[kk][2], aL[kk][3], b0, b1);
            }
        }

        // ---- epilogue from register fragments --------------------------------
        const int b = t >> 10, colbase = (t & 1023) << 7;
        if (MODE != 3) {
            constexpr int SLOT  = (MODE == 0) ? 0 : ((MODE == 2) ? 1 : 2);
            constexpr int CHOFF = (MODE == 0) ? 64 : 0;
            float* dst = (MODE == 0) ? sc_g1 : ((MODE == 1) ? sc_y3 : sc_x1);
#pragma unroll
            for (int half = 0; half < 2; ++half) {
                int r = R0 + lq + half * 8;
                float bias = __ldg(p.bias + r);
                float s = 0.f, q = 0.f;
                float* drow = dst + ((size_t)(b * O + r)) * CPB + colbase + C0;
#pragma unroll
                for (int nt = 0; nt < NT; ++nt) {
                    float v0 = D[nt][half * 2 + 0] + bias;
                    float v1 = D[nt][half * 2 + 1] + bias;
                    if (MODE != 1) { v0 = fmaxf(v0, 0.f); v1 = fmaxf(v1, 0.f); }
                    *(float2*)(drow + nt * 8 + lr * 2) = make_float2(v0, v1);
                    s += v0 + v1;
                    q += v0 * v0 + v1 * v1;
                }
                s += __shfl_xor_sync(0xffffffffu, s, 1);
                s += __shfl_xor_sync(0xffffffffu, s, 2);
                q += __shfl_xor_sync(0xffffffffu, q, 1);
                q += __shfl_xor_sync(0xffffffffu, q, 2);
                if (lr == 0) {
                    atomicAdd(&g_sum[SLOT][b][CHOFF + r], (double)s);
                    atomicAdd(&g_sq [SLOT][b][CHOFF + r], (double)q);
                }
            }
        } else {
            // softmax over K=32 (bias constant over k -> softmax-invariant, omitted)
#pragma unroll
            for (int half = 0; half < 2; ++half) {
                int c = R0 + lq + half * 8;
                float sc3 = g_scale[2][b][c], sh3 = g_shift[2][b][c];
#pragma unroll
                for (int ni = 0; ni < 2; ++ni) {
                    int n = (colbase >> 5) + wcol * 2 + ni;
                    int cnt = __ldg(p.count + b * N_ + n);
                    if (cnt < 1) cnt = 1;
                    float v[8];
                    float mx = -3.0e38f;
#pragma unroll
                    for (int nt2 = 0; nt2 < 4; ++nt2) {
#pragma unroll
                        for (int e = 0; e < 2; ++e) {
                            int k = nt2 * 8 + lr * 2 + e;
                            float x = D[ni * 4 + nt2][half * 2 + e];
                            x = (k < cnt) ? x : -1e9f;
                            v[nt2 * 2 + e] = x;
                            mx = fmaxf(mx, x);
                        }
                    }
                    mx = fmaxf(mx, __shfl_xor_sync(0xffffffffu, mx, 1));
                    mx = fmaxf(mx, __shfl_xor_sync(0xffffffffu, mx, 2));
                    const float* yrow = sc_y3 + ((size_t)(b * 128 + c) * N_ + n) * K_;
                    float num = 0.f, den = 0.f;
#pragma unroll
                    for (int nt2 = 0; nt2 < 4; ++nt2) {
                        float2 y = *(const float2*)(yrow + nt2 * 8 + lr * 2);
                        float e0 = __expf(v[nt2 * 2 + 0] - mx);
                        float e1 = __expf(v[nt2 * 2 + 1] - mx);
                        float g0 = fmaxf(fmaf(sc3, y.x, sh3), 0.f);
                        float g1 = fmaxf(fmaf(sc3, y.y, sh3), 0.f);
                        num += e0 * g0 + e1 * g1;
                        den += e0 + e1;
                    }
                    num += __shfl_xor_sync(0xffffffffu, num, 1);
                    num += __shfl_xor_sync(0xffffffffu, num, 2);
                    den += __shfl_xor_sync(0xffffffffu, den, 1);
                    den += __shfl_xor_sync(0xffffffffu, den, 2);
                    if (lr == 0)
                        p.out[(size_t)(b * 128 + c) * N_ + n] = num / den;
                }
            }
        }

        if (tn < TILES) {
            CP_WAIT0();
            __syncthreads();
            convert(tn);
            __syncthreads();
        }
    }
}

// ---------------------------------------------------------------------------
__global__ void finalize_k(int slot, const float* __restrict__ wgn,
                           const float* __restrict__ bgn) {
    int t = threadIdx.x;
    int b = t >> 7, c = t & 127;
    int g = (c >> 2) << 2;
    double s = g_sum[slot][b][g] + g_sum[slot][b][g + 1] +
               g_sum[slot][b][g + 2] + g_sum[slot][b][g + 3];
    double q = g_sq[slot][b][g] + g_sq[slot][b][g + 1] +
               g_sq[slot][b][g + 2] + g_sq[slot][b][g + 3];
    const double cnte = 4.0 * N_ * K_;
    double mu  = s / cnte;
    double var = q / cnte - mu * mu;
    float rstd = (float)(1.0 / sqrt(var + 1e-5));
    float sc   = wgn[c] * rstd;
    g_scale[slot][b][c] = sc;
    g_shift[slot][b][c] = bgn[c] - (float)mu * sc;
}

// ---------------------------------------------------------------------------
extern "C" void kernel_launch(void* const* d_in, const int* in_sizes, int n_in,
                              void* d_out, int out_size) {
    const float* feat   = (const float*)d_in[0];
    const float* gf     = (const float*)d_in[1];
    const float* gfo    = (const float*)d_in[2];
    const int*   count  = (const int*)  d_in[3];
    const float* W_feat = (const float*)d_in[4];
    const float* b_feat = (const float*)d_in[5];
    const float* W_grp  = (const float*)d_in[6];
    const float* b_grp  = (const float*)d_in[7];
    const float* gn1_w  = (const float*)d_in[8];
    const float* gn1_b  = (const float*)d_in[9];
    const float* W_wc1  = (const float*)d_in[10];
    const float* b_wc1  = (const float*)d_in[11];
    const float* gn2_w  = (const float*)d_in[12];
    const float* gn2_b  = (const float*)d_in[13];
    const float* W_wc2  = (const float*)d_in[14];
    const float* b_wc2  = (const float*)d_in[15];
    const float* W_fo   = (const float*)d_in[16];
    const float* b_fo   = (const float*)d_in[17];
    const float* gn3_w  = (const float*)d_in[18];
    const float* gn3_b  = (const float*)d_in[19];
    float* out = (float*)d_out;

    const int smemBig = 128 * LDB * 4 + 128 * SP * 4;   // 34816 + 67584 = 102400
    const int smemM2  = 128 * LDB * 4 + 64 * SP * 4;    // 34816 + 33792 = 68608
    cudaFuncSetAttribute(hmma_k<0>, cudaFuncAttributeMaxDynamicSharedMemorySize, smemBig);
    cudaFuncSetAttribute(hmma_k<1>, cudaFuncAttributeMaxDynamicSharedMemorySize, smemBig);
    cudaFuncSetAttribute(hmma_k<2>, cudaFuncAttributeMaxDynamicSharedMemorySize, smemM2);
    cudaFuncSetAttribute(hmma_k<3>, cudaFuncAttributeMaxDynamicSharedMemorySize, smemBig);

    const int GRID = 148;

    zero_stats_k<<<2, 1024>>>();
    feat1_k<<<dim3(N_ / 32, B_), 256>>>(feat, W_feat, b_feat);

    { Ptrs p{gf,  W_grp, b_grp, nullptr, nullptr};
      hmma_k<0><<<GRID, 512, smemBig>>>(p); }     // g1 + gn1 stats (ch 64+)
    { Ptrs p{gfo, W_fo,  b_fo,  nullptr, nullptr};
      hmma_k<1><<<GRID, 512, smemBig>>>(p); }     // y3 + gn3 stats

    finalize_k<<<1, 512>>>(0, gn1_w, gn1_b);
    finalize_k<<<1, 512>>>(2, gn3_w, gn3_b);

    { Ptrs p{nullptr, W_wc1, b_wc1, nullptr, nullptr};
      hmma_k<2><<<GRID, 512, smemM2>>>(p); }      // x1 + gn2 stats

    finalize_k<<<1, 512>>>(1, gn2_w, gn2_b);

    { Ptrs p{nullptr, W_wc2, b_wc2, count, out};
      hmma_k<3><<<GRID, 512, smemBig>>>(p); }     // scores -> softmax -> out
}

// round 6
// speedup vs baseline: 5.3458x; 1.0770x over previous
#include <cuda_runtime.h>
#include <cuda_fp16.h>
#include <cstdint>
#include <cstddef>

// ---------------------------------------------------------------------------
constexpr int B_ = 4;
constexpr int N_ = 4096;
constexpr int K_ = 32;
constexpr int CPB = N_ * K_;              // 131072 columns per batch
constexpr int TPB = CPB / 128;            // 1024 tiles per batch
constexpr int TILES = B_ * TPB;           // 4096
constexpr int LDB = 68;                   // u32 stride per n-col of B tile
constexpr int SP  = 132;                  // fp32 stage row stride

// ---------------------------------------------------------------------------
// Scratch: packed fp16 intermediates (B-fragment layout for direct cp.async)
// ---------------------------------------------------------------------------
__device__ uint32_t feat1p[B_][N_][32];                    //   2 MB
__device__ uint32_t g1p [(size_t)B_ * TPB * 128 * 32];     //  64 MB
__device__ uint32_t x1p [(size_t)B_ * TPB * 128 * 64];     // 128 MB
__device__ __half   y3h [(size_t)B_ * 128 * CPB];          // 128 MB

__device__ double g_sum  [3][B_][128];
__device__ double g_sq   [3][B_][128];
__device__ float  g_scale[3][B_][128];
__device__ float  g_shift[3][B_][128];

// ---------------------------------------------------------------------------
__device__ __forceinline__ uint32_t smem_to_u32(const void* p) {
    uint32_t a;
    asm("{ .reg .u64 t; cvta.to.shared.u64 t, %1; cvt.u32.u64 %0, t; }"
        : "=r"(a) : "l"(p));
    return a;
}
__device__ __forceinline__ void cp_async16(uint32_t dst, const void* src) {
    asm volatile("cp.async.cg.shared.global [%0], [%1], 16;" :: "r"(dst), "l"(src));
}
__device__ __forceinline__ void cp_async16_ca(uint32_t dst, const void* src) {
    asm volatile("cp.async.ca.shared.global [%0], [%1], 16;" :: "r"(dst), "l"(src));
}
#define CP_COMMIT() asm volatile("cp.async.commit_group;" ::: "memory")
#define CP_WAIT0()  asm volatile("cp.async.wait_group 0;" ::: "memory")

#define MMA_F16(d, a0, a1, a2, a3, b0, b1) \
    asm volatile("mma.sync.aligned.m16n8k16.row.col.f32.f16.f16.f32 " \
        "{%0,%1,%2,%3},{%4,%5,%6,%7},{%8,%9},{%0,%1,%2,%3};" \
        : "+f"((d)[0]), "+f"((d)[1]), "+f"((d)[2]), "+f"((d)[3]) \
        : "r"(a0), "r"(a1), "r"(a2), "r"(a3), "r"(b0), "r"(b1))

__device__ __forceinline__ uint32_t packh(float x0, float x1) {
    __half2 h = __float22half2_rn(make_float2(x0, x1));
    return *(uint32_t*)&h;
}
__device__ __forceinline__ void splith(float x0, float x1, uint32_t& hi, uint32_t& lo) {
    __half2 h = __float22half2_rn(make_float2(x0, x1));
    float2 hf = __half22float2(h);
    __half2 l = __float22half2_rn(make_float2(x0 - hf.x, x1 - hf.y));
    hi = *(uint32_t*)&h;
    lo = *(uint32_t*)&l;
}

// ---------------------------------------------------------------------------
__global__ void zero_stats_k() {
    int t = blockIdx.x * blockDim.x + threadIdx.x;
    if (t < 3 * B_ * 128) {
        (&g_sum[0][0][0])[t] = 0.0;
        (&g_sq [0][0][0])[t] = 0.0;
    }
}

// ---------------------------------------------------------------------------
// feat1 = relu(W_feat @ feat + b): packed fp16 into feat1p + gn1 stats (ch<64)
// ---------------------------------------------------------------------------
__global__ void __launch_bounds__(256) feat1_k(const float* __restrict__ feat,
                                               const float* __restrict__ Wf,
                                               const float* __restrict__ bf) {
    __shared__ float Ws[64 * 128];
    __shared__ float Fs[128 * 32];
    const int b  = blockIdx.y;
    const int n0 = blockIdx.x * 32;
    const int tid = threadIdx.x;

    for (int idx = tid; idx < 64 * 128; idx += 256) Ws[idx] = Wf[idx];
    for (int idx = tid; idx < 128 * 32; idx += 256) {
        int c = idx >> 5, jj = idx & 31;
        Fs[idx] = feat[(size_t)(b * 128 + c) * N_ + n0 + jj];
    }
    __syncthreads();

    const int jj = tid & 31;
    const int w  = tid >> 5;
    float acc[8];
#pragma unroll
    for (int oi = 0; oi < 8; ++oi) acc[oi] = __ldg(bf + w * 8 + oi);
#pragma unroll 4
    for (int c = 0; c < 128; ++c) {
        float x = Fs[c * 32 + jj];
#pragma unroll
        for (int oi = 0; oi < 8; ++oi)
            acc[oi] = fmaf(Ws[(w * 8 + oi) * 128 + c], x, acc[oi]);
    }
#pragma unroll
    for (int oi = 0; oi < 8; ++oi) acc[oi] = fmaxf(acc[oi], 0.f);

    // stats (weight 32 for K broadcast)
#pragma unroll
    for (int oi = 0; oi < 8; ++oi) {
        float s = acc[oi], q = acc[oi] * acc[oi];
#pragma unroll
        for (int off = 16; off; off >>= 1) {
            s += __shfl_xor_sync(0xffffffffu, s, off);
            q += __shfl_xor_sync(0xffffffffu, q, off);
        }
        if (jj == 0) {
            atomicAdd(&g_sum[0][b][w * 8 + oi], (double)(32.0f * s));
            atomicAdd(&g_sq [0][b][w * 8 + oi], (double)(32.0f * q));
        }
    }
    // pack fp16 pairs
    uint4 pk;
    pk.x = packh(acc[0], acc[1]);
    pk.y = packh(acc[2], acc[3]);
    pk.z = packh(acc[4], acc[5]);
    pk.w = packh(acc[6], acc[7]);
    *(uint4*)&feat1p[b][n0 + jj][w * 4] = pk;
}

// ---------------------------------------------------------------------------
struct Ptrs {
    const float* X;
    const float* W;
    const float* bias;
    const int*   count;
    float*       out;
};

template <int MODE>
__global__ void __launch_bounds__(512, 1) hmma_k(Ptrs p) {
    constexpr bool DIRECT = (MODE >= 2);
    constexpr int O  = (MODE == 0) ? 64 : 128;
    constexpr int NT = (MODE == 0) ? 4 : 8;
    constexpr int CW = NT * 8;

    extern __shared__ char smem[];
    uint32_t* Bh0 = (uint32_t*)smem;
    uint32_t* Bh1 = Bh0 + 128 * LDB;               // DIRECT only
    float* stage  = (float*)(Bh0 + 128 * LDB);     // !DIRECT only
    const uint32_t stage_u = smem_to_u32(stage);
    const uint32_t bh0_u = smem_to_u32(Bh0);
    const uint32_t bh1_u = smem_to_u32(Bh1);

    const int tid = threadIdx.x;
    const int wid = tid >> 5, lane = tid & 31;
    const int lq = lane >> 2, lr = lane & 3;
    const int wrow = (MODE == 0) ? (wid >> 2) : (wid >> 1);
    const int wcol = (MODE == 0) ? (wid & 3) : (wid & 1);
    const int R0 = wrow * 16, C0 = wcol * CW;

    uint32_t aH[8][4], aL[8][4];
    float bias0 = 0.f, bias1 = 0.f;

    auto build_A = [&](int b) {
        constexpr int SLOT = (MODE == 2) ? 0 : 1;
#pragma unroll
        for (int kk = 0; kk < 8; ++kk) {
            int kb = kk * 16 + lr * 2;
            float s0 = 1.f, s1 = 1.f, s2 = 1.f, s3 = 1.f;
            if (DIRECT) {
                s0 = g_scale[SLOT][b][kb];
                s1 = g_scale[SLOT][b][kb + 1];
                s2 = g_scale[SLOT][b][kb + 8];
                s3 = g_scale[SLOT][b][kb + 9];
            }
            const float* w0 = p.W + (R0 + lq) * 128 + kb;
            const float* w1 = p.W + (R0 + lq + 8) * 128 + kb;
            float2 f0 = *(const float2*)(w0);
            float2 f1 = *(const float2*)(w1);
            float2 f2 = *(const float2*)(w0 + 8);
            float2 f3 = *(const float2*)(w1 + 8);
            splith(f0.x * s0, f0.y * s1, aH[kk][0], aL[kk][0]);
            splith(f1.x * s0, f1.y * s1, aH[kk][1], aL[kk][1]);
            splith(f2.x * s2, f2.y * s3, aH[kk][2], aL[kk][2]);
            splith(f3.x * s2, f3.y * s3, aH[kk][3], aL[kk][3]);
        }
        if (MODE == 2) {
            float a0 = 0.f, a1 = 0.f;
            for (int c = lr; c < 128; c += 4) {
                float sh = g_shift[0][b][c];
                a0 = fmaf(__ldg(p.W + (R0 + lq) * 128 + c), sh, a0);
                a1 = fmaf(__ldg(p.W + (R0 + lq + 8) * 128 + c), sh, a1);
            }
            a0 += __shfl_xor_sync(0xffffffffu, a0, 1);
            a0 += __shfl_xor_sync(0xffffffffu, a0, 2);
            a1 += __shfl_xor_sync(0xffffffffu, a1, 1);
            a1 += __shfl_xor_sync(0xffffffffu, a1, 2);
            bias0 = __ldg(p.bias + R0 + lq) + a0;
            bias1 = __ldg(p.bias + R0 + lq + 8) + a1;
        } else if (MODE != 3) {
            bias0 = __ldg(p.bias + R0 + lq);
            bias1 = __ldg(p.bias + R0 + lq + 8);
        }
    };

    auto load_stage = [&](int t) {          // modes 0/1: fp32 input
        int b = t >> 10, colbase = (t & 1023) << 7;
        for (int idx = tid; idx < 128 * 32; idx += 512) {
            int ch = idx >> 5, c4 = (idx & 31) << 2;
            cp_async16(stage_u + (uint32_t)(ch * SP + c4) * 4u,
                       p.X + ((size_t)(b * 128 + ch)) * CPB + colbase + c4);
        }
        CP_COMMIT();
    };

    auto convert = [&]() {                   // stage fp32 -> Bh0 fp16
        const int col = wid * 8 + lq;
#pragma unroll
        for (int j = 0; j < 16; ++j) {
            int k = lr + 4 * j;
            int ch = 2 * k;
            float x0 = stage[ch * SP + col];
            float x1 = stage[ch * SP + SP + col];
            Bh0[col * LDB + k] = packh(x0, x1);
        }
    };

    auto load_direct = [&](int t, uint32_t bh_u) {   // modes 2/3
        int b = t >> 10, tt = t & 1023;
        if (MODE == 3) {
            const uint32_t* base = x1p + ((size_t)(b * 1024 + tt) * 128) * 64;
            for (int idx = tid; idx < 2048; idx += 512) {
                int col = idx >> 4, chunk = idx & 15;
                cp_async16(bh_u + (uint32_t)(col * LDB + chunk * 4) * 4u,
                           base + col * 64 + chunk * 4);
            }
        } else {
            const uint32_t* gbase = g1p + ((size_t)(b * 1024 + tt) * 128) * 32;
            for (int idx = tid; idx < 2048; idx += 512) {
                int col = idx >> 4, chunk = idx & 15;
                if (chunk < 8) {
                    int n = tt * 4 + (col >> 5);
                    cp_async16_ca(bh_u + (uint32_t)(col * LDB + chunk * 4) * 4u,
                                  &feat1p[b][n][chunk * 4]);
                } else {
                    cp_async16(bh_u + (uint32_t)(col * LDB + 32 + (chunk - 8) * 4) * 4u,
                               gbase + col * 32 + (chunk - 8) * 4);
                }
            }
        }
        CP_COMMIT();
    };

    // ---- epilogue helper pieces shared by modes -----------------------------
    auto run_tile = [&](uint32_t* Bcur, int t) {
        const int b = t >> 10, tt = t & 1023;
        const int colbase = tt << 7;

        float D[NT][4];
#pragma unroll
        for (int nt = 0; nt < NT; ++nt)
#pragma unroll
            for (int e = 0; e < 4; ++e) D[nt][e] = 0.f;

#pragma unroll
        for (int kk = 0; kk < 8; ++kk) {
#pragma unroll
            for (int nt = 0; nt < NT; ++nt) {
                int n = C0 + nt * 8 + lq;
                uint32_t b0 = Bcur[n * LDB + kk * 8 + lr];
                uint32_t b1 = Bcur[n * LDB + kk * 8 + 4 + lr];
                MMA_F16(D[nt], aH[kk][0], aH[kk][1], aH[kk][2], aH[kk][3], b0, b1);
                MMA_F16(D[nt], aL[kk][0], aL[kk][1], aL[kk][2], aL[kk][3], b0, b1);
            }
        }

        if (MODE == 0 || MODE == 2) {
            constexpr int SLOT  = (MODE == 0) ? 0 : 1;
            constexpr int CHOFF = (MODE == 0) ? 64 : 0;
            constexpr int MST   = (MODE == 0) ? 32 : 64;   // pair stride per col
            uint32_t* gdst = (MODE == 0)
                ? g1p + ((size_t)(b * 1024 + tt) * 128) * 32
                : x1p + ((size_t)(b * 1024 + tt) * 128) * 64;
#pragma unroll
            for (int half = 0; half < 2; ++half) {
                int r = R0 + lq + half * 8;
                float bias = half ? bias1 : bias0;
                int m = (R0 >> 1) + (lq >> 1) + 4 * half;
                float s = 0.f, q = 0.f;
#pragma unroll
                for (int nt = 0; nt < NT; ++nt) {
                    float v0 = fmaxf(D[nt][half * 2 + 0] + bias, 0.f);
                    float v1 = fmaxf(D[nt][half * 2 + 1] + bias, 0.f);
                    s += v0 + v1; q += v0 * v0 + v1 * v1;
                    float pv0 = __shfl_xor_sync(0xffffffffu, v0, 4);
                    float pv1 = __shfl_xor_sync(0xffffffffu, v1, 4);
                    if (!(lq & 1)) {
                        int col = C0 + nt * 8 + lr * 2;
                        gdst[(size_t)col * MST + m]       = packh(v0, pv0);
                        gdst[(size_t)(col + 1) * MST + m] = packh(v1, pv1);
                    }
                }
                s += __shfl_xor_sync(0xffffffffu, s, 1);
                s += __shfl_xor_sync(0xffffffffu, s, 2);
                q += __shfl_xor_sync(0xffffffffu, q, 1);
                q += __shfl_xor_sync(0xffffffffu, q, 2);
                if (lr == 0) {
                    atomicAdd(&g_sum[SLOT][b][CHOFF + r], (double)s);
                    atomicAdd(&g_sq [SLOT][b][CHOFF + r], (double)q);
                }
            }
        } else if (MODE == 1) {
#pragma unroll
            for (int half = 0; half < 2; ++half) {
                int r = R0 + lq + half * 8;
                float bias = half ? bias1 : bias0;
                float s = 0.f, q = 0.f;
                __half* drow = y3h + (size_t)(b * 128 + r) * CPB + colbase + C0;
#pragma unroll
                for (int nt = 0; nt < NT; ++nt) {
                    float v0 = D[nt][half * 2 + 0] + bias;
                    float v1 = D[nt][half * 2 + 1] + bias;
                    s += v0 + v1; q += v0 * v0 + v1 * v1;
                    *(uint32_t*)(drow + nt * 8 + lr * 2) = packh(v0, v1);
                }
                s += __shfl_xor_sync(0xffffffffu, s, 1);
                s += __shfl_xor_sync(0xffffffffu, s, 2);
                q += __shfl_xor_sync(0xffffffffu, q, 1);
                q += __shfl_xor_sync(0xffffffffu, q, 2);
                if (lr == 0) {
                    atomicAdd(&g_sum[2][b][r], (double)s);
                    atomicAdd(&g_sq [2][b][r], (double)q);
                }
            }
        } else { // MODE 3: masked softmax + gn3(y3h) relu + weighted sum
#pragma unroll
            for (int half = 0; half < 2; ++half) {
                int c = R0 + lq + half * 8;
                float sc3 = g_scale[2][b][c], sh3 = g_shift[2][b][c];
#pragma unroll
                for (int ni = 0; ni < 2; ++ni) {
                    int n = (colbase >> 5) + wcol * 2 + ni;
                    int cnt = __ldg(p.count + b * N_ + n);
                    if (cnt < 1) cnt = 1;
                    float v[8];
                    float mx = -3.0e38f;
#pragma unroll
                    for (int nt2 = 0; nt2 < 4; ++nt2) {
#pragma unroll
                        for (int e = 0; e < 2; ++e) {
                            int k = nt2 * 8 + lr * 2 + e;
                            float x = D[ni * 4 + nt2][half * 2 + e];
                            x = (k < cnt) ? x : -1e9f;
                            v[nt2 * 2 + e] = x;
                            mx = fmaxf(mx, x);
                        }
                    }
                    mx = fmaxf(mx, __shfl_xor_sync(0xffffffffu, mx, 1));
                    mx = fmaxf(mx, __shfl_xor_sync(0xffffffffu, mx, 2));
                    const __half* yrow = y3h + (size_t)(b * 128 + c) * CPB + n * 32;
                    float num = 0.f, den = 0.f;
#pragma unroll
                    for (int nt2 = 0; nt2 < 4; ++nt2) {
                        __half2 y2 = *(const __half2*)(yrow + nt2 * 8 + lr * 2);
                        float2 y = __half22float2(y2);
                        float e0 = __expf(v[nt2 * 2 + 0] - mx);
                        float e1 = __expf(v[nt2 * 2 + 1] - mx);
                        float g0 = fmaxf(fmaf(sc3, y.x, sh3), 0.f);
                        float g1 = fmaxf(fmaf(sc3, y.y, sh3), 0.f);
                        num += e0 * g0 + e1 * g1;
                        den += e0 + e1;
                    }
                    num += __shfl_xor_sync(0xffffffffu, num, 1);
                    num += __shfl_xor_sync(0xffffffffu, num, 2);
                    den += __shfl_xor_sync(0xffffffffu, den, 1);
                    den += __shfl_xor_sync(0xffffffffu, den, 2);
                    if (lr == 0)
                        p.out[(size_t)(b * 128 + c) * N_ + n] = num / den;
                }
            }
        }
    };

    // ---- main loops ----------------------------------------------------------
    const int G = gridDim.x;
    int cur_b = blockIdx.x >> 10;
    build_A(cur_b);

    if (DIRECT) {
        load_direct(blockIdx.x, bh0_u);
        CP_WAIT0();
        __syncthreads();
        int cur = 0;
        for (int t = blockIdx.x; t < TILES; t += G) {
            int b = t >> 10;
            if (b != cur_b) { cur_b = b; build_A(b); }
            int tn = t + G;
            if (tn < TILES) load_direct(tn, cur ? bh0_u : bh1_u);
            run_tile(cur ? Bh1 : Bh0, t);
            CP_WAIT0();
            __syncthreads();
            cur ^= 1;
        }
    } else {
        load_stage(blockIdx.x);
        CP_WAIT0();
        __syncthreads();
        convert();
        __syncthreads();
        for (int t = blockIdx.x; t < TILES; t += G) {
            int tn = t + G;
            if (tn < TILES) load_stage(tn);
            run_tile(Bh0, t);
            if (tn < TILES) {
                CP_WAIT0();
                __syncthreads();
                convert();
                __syncthreads();
            }
        }
    }
}

// ---------------------------------------------------------------------------
__global__ void finalize_k(int slot, const float* __restrict__ wgn,
                           const float* __restrict__ bgn) {
    int t = threadIdx.x;
    int b = t >> 7, c = t & 127;
    int g = (c >> 2) << 2;
    double s = g_sum[slot][b][g] + g_sum[slot][b][g + 1] +
               g_sum[slot][b][g + 2] + g_sum[slot][b][g + 3];
    double q = g_sq[slot][b][g] + g_sq[slot][b][g + 1] +
               g_sq[slot][b][g + 2] + g_sq[slot][b][g + 3];
    const double cnte = 4.0 * N_ * K_;
    double mu  = s / cnte;
    double var = q / cnte - mu * mu;
    float rstd = (float)(1.0 / sqrt(var + 1e-5));
    float sc   = wgn[c] * rstd;
    g_scale[slot][b][c] = sc;
    g_shift[slot][b][c] = bgn[c] - (float)mu * sc;
}

// ---------------------------------------------------------------------------
extern "C" void kernel_launch(void* const* d_in, const int* in_sizes, int n_in,
                              void* d_out, int out_size) {
    const float* feat   = (const float*)d_in[0];
    const float* gf     = (const float*)d_in[1];
    const float* gfo    = (const float*)d_in[2];
    const int*   count  = (const int*)  d_in[3];
    const float* W_feat = (const float*)d_in[4];
    const float* b_feat = (const float*)d_in[5];
    const float* W_grp  = (const float*)d_in[6];
    const float* b_grp  = (const float*)d_in[7];
    const float* gn1_w  = (const float*)d_in[8];
    const float* gn1_b  = (const float*)d_in[9];
    const float* W_wc1  = (const float*)d_in[10];
    const float* b_wc1  = (const float*)d_in[11];
    const float* gn2_w  = (const float*)d_in[12];
    const float* gn2_b  = (const float*)d_in[13];
    const float* W_wc2  = (const float*)d_in[14];
    const float* b_wc2  = (const float*)d_in[15];
    const float* W_fo   = (const float*)d_in[16];
    const float* b_fo   = (const float*)d_in[17];
    const float* gn3_w  = (const float*)d_in[18];
    const float* gn3_b  = (const float*)d_in[19];
    float* out = (float*)d_out;

    const int smemConv   = 128 * LDB * 4 + 128 * SP * 4;   // 102400 (modes 0/1)
    const int smemDirect = 2 * 128 * LDB * 4;              //  69632 (modes 2/3)
    cudaFuncSetAttribute(hmma_k<0>, cudaFuncAttributeMaxDynamicSharedMemorySize, smemConv);
    cudaFuncSetAttribute(hmma_k<1>, cudaFuncAttributeMaxDynamicSharedMemorySize, smemConv);
    cudaFuncSetAttribute(hmma_k<2>, cudaFuncAttributeMaxDynamicSharedMemorySize, smemDirect);
    cudaFuncSetAttribute(hmma_k<3>, cudaFuncAttributeMaxDynamicSharedMemorySize, smemDirect);

    const int GRID = 148;

    zero_stats_k<<<2, 1024>>>();
    feat1_k<<<dim3(N_ / 32, B_), 256>>>(feat, W_feat, b_feat);

    { Ptrs p{gf,  W_grp, b_grp, nullptr, nullptr};
      hmma_k<0><<<GRID, 512, smemConv>>>(p); }      // g1p + gn1 stats (ch 64+)
    { Ptrs p{gfo, W_fo,  b_fo,  nullptr, nullptr};
      hmma_k<1><<<GRID, 512, smemConv>>>(p); }      // y3h + gn3 stats

    finalize_k<<<1, 512>>>(0, gn1_w, gn1_b);
    finalize_k<<<1, 512>>>(2, gn3_w, gn3_b);

    { Ptrs p{nullptr, W_wc1, b_wc1, nullptr, nullptr};
      hmma_k<2><<<GRID, 512, smemDirect>>>(p); }    // x1p + gn2 stats

    finalize_k<<<1, 512>>>(1, gn2_w, gn2_b);

    { Ptrs p{nullptr, W_wc2, b_wc2, count, out};
      hmma_k<3><<<GRID, 512, smemDirect>>>(p); }    // scores -> softmax -> out
}

// round 7
// speedup vs baseline: 6.2267x; 1.1648x over previous
#include <cuda_runtime.h>
#include <cuda_fp16.h>
#include <cstdint>
#include <cstddef>

// ---------------------------------------------------------------------------
constexpr int B_ = 4;
constexpr int N_ = 4096;
constexpr int K_ = 32;
constexpr int CPB = N_ * K_;              // 131072 columns per batch
constexpr int TPB = CPB / 128;            // 1024 full tiles per batch
constexpr int LDB = 68;                   // u32 stride per n-col of B tile

// ---------------------------------------------------------------------------
// Scratch: packed fp16 intermediates (B-fragment layout for direct cp.async)
// ---------------------------------------------------------------------------
__device__ uint32_t feat1p[B_][N_][32];                    //   2 MB
__device__ uint32_t g1p [(size_t)B_ * TPB * 128 * 32];     //  64 MB
__device__ uint32_t x1p [(size_t)B_ * TPB * 128 * 64];     // 128 MB
__device__ __half   y3h [(size_t)B_ * 128 * CPB];          // 128 MB

__device__ double g_sum  [3][B_][128];
__device__ double g_sq   [3][B_][128];
__device__ float  g_scale[3][B_][128];
__device__ float  g_shift[3][B_][128];

// ---------------------------------------------------------------------------
__device__ __forceinline__ uint32_t smem_to_u32(const void* p) {
    uint32_t a;
    asm("{ .reg .u64 t; cvta.to.shared.u64 t, %1; cvt.u32.u64 %0, t; }"
        : "=r"(a) : "l"(p));
    return a;
}
__device__ __forceinline__ void cp_async16(uint32_t dst, const void* src) {
    asm volatile("cp.async.cg.shared.global [%0], [%1], 16;" :: "r"(dst), "l"(src));
}
__device__ __forceinline__ void cp_async16_ca(uint32_t dst, const void* src) {
    asm volatile("cp.async.ca.shared.global [%0], [%1], 16;" :: "r"(dst), "l"(src));
}
#define CP_COMMIT() asm volatile("cp.async.commit_group;" ::: "memory")
#define CP_WAIT0()  asm volatile("cp.async.wait_group 0;" ::: "memory")

#define MMA_F16(d, a0, a1, a2, a3, b0, b1) \
    asm volatile("mma.sync.aligned.m16n8k16.row.col.f32.f16.f16.f32 " \
        "{%0,%1,%2,%3},{%4,%5,%6,%7},{%8,%9},{%0,%1,%2,%3};" \
        : "+f"((d)[0]), "+f"((d)[1]), "+f"((d)[2]), "+f"((d)[3]) \
        : "r"(a0), "r"(a1), "r"(a2), "r"(a3), "r"(b0), "r"(b1))

__device__ __forceinline__ uint32_t packh(float x0, float x1) {
    __half2 h = __float22half2_rn(make_float2(x0, x1));
    return *(uint32_t*)&h;
}
__device__ __forceinline__ void splith(float x0, float x1, uint32_t& hi, uint32_t& lo) {
    __half2 h = __float22half2_rn(make_float2(x0, x1));
    float2 hf = __half22float2(h);
    __half2 l = __float22half2_rn(make_float2(x0 - hf.x, x1 - hf.y));
    hi = *(uint32_t*)&h;
    lo = *(uint32_t*)&l;
}

// ---------------------------------------------------------------------------
__global__ void zero_stats_k() {
    int t = blockIdx.x * blockDim.x + threadIdx.x;
    if (t < 3 * B_ * 128) {
        (&g_sum[0][0][0])[t] = 0.0;
        (&g_sq [0][0][0])[t] = 0.0;
    }
}

// ---------------------------------------------------------------------------
// feat1 = relu(W_feat @ feat + b): packed fp16 into feat1p + gn1 stats (ch<64)
// ---------------------------------------------------------------------------
__global__ void __launch_bounds__(256) feat1_k(const float* __restrict__ feat,
                                               const float* __restrict__ Wf,
                                               const float* __restrict__ bf) {
    __shared__ float Ws[64 * 128];
    __shared__ float Fs[128 * 32];
    const int b  = blockIdx.y;
    const int n0 = blockIdx.x * 32;
    const int tid = threadIdx.x;

    for (int idx = tid; idx < 64 * 128; idx += 256) Ws[idx] = Wf[idx];
    for (int idx = tid; idx < 128 * 32; idx += 256) {
        int c = idx >> 5, jj = idx & 31;
        Fs[idx] = feat[(size_t)(b * 128 + c) * N_ + n0 + jj];
    }
    __syncthreads();

    const int jj = tid & 31;
    const int w  = tid >> 5;
    float acc[8];
#pragma unroll
    for (int oi = 0; oi < 8; ++oi) acc[oi] = __ldg(bf + w * 8 + oi);
#pragma unroll 4
    for (int c = 0; c < 128; ++c) {
        float x = Fs[c * 32 + jj];
#pragma unroll
        for (int oi = 0; oi < 8; ++oi)
            acc[oi] = fmaf(Ws[(w * 8 + oi) * 128 + c], x, acc[oi]);
    }
#pragma unroll
    for (int oi = 0; oi < 8; ++oi) acc[oi] = fmaxf(acc[oi], 0.f);

#pragma unroll
    for (int oi = 0; oi < 8; ++oi) {
        float s = acc[oi], q = acc[oi] * acc[oi];
#pragma unroll
        for (int off = 16; off; off >>= 1) {
            s += __shfl_xor_sync(0xffffffffu, s, off);
            q += __shfl_xor_sync(0xffffffffu, q, off);
        }
        if (jj == 0) {
            atomicAdd(&g_sum[0][b][w * 8 + oi], (double)(32.0f * s));
            atomicAdd(&g_sq [0][b][w * 8 + oi], (double)(32.0f * q));
        }
    }
    uint4 pk;
    pk.x = packh(acc[0], acc[1]);
    pk.y = packh(acc[2], acc[3]);
    pk.z = packh(acc[4], acc[5]);
    pk.w = packh(acc[6], acc[7]);
    *(uint4*)&feat1p[b][n0 + jj][w * 4] = pk;
}

// ---------------------------------------------------------------------------
struct Ptrs {
    const float* X;
    const float* W;
    const float* bias;
    const int*   count;
    float*       out;
};

// MODE 0: g1p = relu(W_grp@gf+b), full tiles (128 col), warps 4x2
// MODE 1: y3h = W_fo@gfo+b, half tiles (64 col), warps 8x1
// MODE 2: x1p = relu(Wwc1*gn1scale @ concat + b'), half tiles, direct fp16 in
// MODE 3: softmax(Wwc2*gn2scale @ x1p) * relu(gn3(y3h)) summed, half tiles
template <int MODE>
__global__ void __launch_bounds__(256, 2) hmma_k(Ptrs p) {
    constexpr bool DIRECT = (MODE >= 2);
    constexpr int COLS  = (MODE == 0) ? 128 : 64;
    constexpr int UNITS = B_ * (CPB / COLS);       // 4096 or 8192
    constexpr int NT    = 8;                       // n8 tiles per warp (CW=64)
    constexpr int SPM   = (MODE == 0) ? 132 : 68;  // stage row stride

    extern __shared__ char smem[];
    uint32_t* Bh0 = (uint32_t*)smem;
    uint32_t* Bh1 = Bh0 + COLS * LDB;              // DIRECT double buffer
    float* stage  = (float*)(Bh0 + COLS * LDB);    // !DIRECT
    const uint32_t stage_u = smem_to_u32(stage);
    const uint32_t bh0_u = smem_to_u32(Bh0);
    const uint32_t bh1_u = smem_to_u32(Bh1);

    const int tid = threadIdx.x;
    const int wid = tid >> 5, lane = tid & 31;
    const int lq = lane >> 2, lr = lane & 3;
    const int wrow = (MODE == 0) ? (wid >> 1) : wid;
    const int wcol = (MODE == 0) ? (wid & 1) : 0;
    const int R0 = wrow * 16, C0 = wcol * 64;

    uint32_t aH[8][4], aL[8][4];
    float bias0 = 0.f, bias1 = 0.f;

    auto build_A = [&](int b) {
        constexpr int SLOT = (MODE == 2) ? 0 : 1;
#pragma unroll
        for (int kk = 0; kk < 8; ++kk) {
            int kb = kk * 16 + lr * 2;
            float s0 = 1.f, s1 = 1.f, s2 = 1.f, s3 = 1.f;
            if (DIRECT) {
                s0 = g_scale[SLOT][b][kb];
                s1 = g_scale[SLOT][b][kb + 1];
                s2 = g_scale[SLOT][b][kb + 8];
                s3 = g_scale[SLOT][b][kb + 9];
            }
            const float* w0 = p.W + (R0 + lq) * 128 + kb;
            const float* w1 = p.W + (R0 + lq + 8) * 128 + kb;
            float2 f0 = *(const float2*)(w0);
            float2 f1 = *(const float2*)(w1);
            float2 f2 = *(const float2*)(w0 + 8);
            float2 f3 = *(const float2*)(w1 + 8);
            splith(f0.x * s0, f0.y * s1, aH[kk][0], aL[kk][0]);
            splith(f1.x * s0, f1.y * s1, aH[kk][1], aL[kk][1]);
            splith(f2.x * s2, f2.y * s3, aH[kk][2], aL[kk][2]);
            splith(f3.x * s2, f3.y * s3, aH[kk][3], aL[kk][3]);
        }
        if (MODE == 2) {
            float a0 = 0.f, a1 = 0.f;
            for (int c = lr; c < 128; c += 4) {
                float sh = g_shift[0][b][c];
                a0 = fmaf(__ldg(p.W + (R0 + lq) * 128 + c), sh, a0);
                a1 = fmaf(__ldg(p.W + (R0 + lq + 8) * 128 + c), sh, a1);
            }
            a0 += __shfl_xor_sync(0xffffffffu, a0, 1);
            a0 += __shfl_xor_sync(0xffffffffu, a0, 2);
            a1 += __shfl_xor_sync(0xffffffffu, a1, 1);
            a1 += __shfl_xor_sync(0xffffffffu, a1, 2);
            bias0 = __ldg(p.bias + R0 + lq) + a0;
            bias1 = __ldg(p.bias + R0 + lq + 8) + a1;
        } else if (MODE != 3) {
            bias0 = __ldg(p.bias + R0 + lq);
            bias1 = __ldg(p.bias + R0 + lq + 8);
        }
    };

    // unit decode
    auto unit_b   = [&](int u) { return (MODE == 0) ? (u >> 10) : (u >> 11); };
    auto unit_col = [&](int u) {   // global column base
        if (MODE == 0) return (u & 1023) << 7;
        int h = u & 2047;
        return (h >> 1) * 128 + (h & 1) * 64;
    };

    auto load_stage = [&](int u) {           // modes 0/1 (fp32 input)
        int b = unit_b(u), colbase = unit_col(u);
        for (int idx = tid; idx < 128 * (COLS / 4); idx += 256) {
            int ch = idx / (COLS / 4), c4 = (idx % (COLS / 4)) << 2;
            cp_async16(stage_u + (uint32_t)(ch * SPM + c4) * 4u,
                       p.X + ((size_t)(b * 128 + ch)) * CPB + colbase + c4);
        }
        CP_COMMIT();
    };

    auto convert = [&]() {                    // stage fp32 -> Bh0 fp16
        for (int s = tid; s < COLS * 4; s += 256) {
            int col = s >> 2, r4 = s & 3;
#pragma unroll
            for (int j = 0; j < 16; ++j) {
                int k = r4 + 4 * j;
                int ch = 2 * k;
                float x0 = stage[ch * SPM + col];
                float x1 = stage[ch * SPM + SPM + col];
                Bh0[col * LDB + k] = packh(x0, x1);
            }
        }
    };

    auto load_direct = [&](int u, uint32_t bh_u) {   // modes 2/3, 64 cols
        int b = unit_b(u);
        int h = u & 2047, tt = h >> 1, half = h & 1;
        if (MODE == 3) {
            const uint32_t* base =
                x1p + ((size_t)(b * 1024 + tt) * 128 + half * 64) * 64;
            for (int idx = tid; idx < 1024; idx += 256) {
                int col = idx >> 4, chunk = idx & 15;
                cp_async16(bh_u + (uint32_t)(col * LDB + chunk * 4) * 4u,
                           base + col * 64 + chunk * 4);
            }
        } else {
            const uint32_t* gbase =
                g1p + ((size_t)(b * 1024 + tt) * 128 + half * 64) * 32;
            int colbase = tt * 128 + half * 64;
            for (int idx = tid; idx < 1024; idx += 256) {
                int col = idx >> 4, chunk = idx & 15;
                if (chunk < 8) {
                    int n = (colbase + col) >> 5;
                    cp_async16_ca(bh_u + (uint32_t)(col * LDB + chunk * 4) * 4u,
                                  &feat1p[b][n][chunk * 4]);
                } else {
                    cp_async16(bh_u + (uint32_t)(col * LDB + 32 + (chunk - 8) * 4) * 4u,
                               gbase + col * 32 + (chunk - 8) * 4);
                }
            }
        }
        CP_COMMIT();
    };

    auto run_tile = [&](uint32_t* Bcur, int u) {
        const int b = unit_b(u), colbase = unit_col(u);

        float D[NT][4];
#pragma unroll
        for (int nt = 0; nt < NT; ++nt)
#pragma unroll
            for (int e = 0; e < 4; ++e) D[nt][e] = 0.f;

#pragma unroll
        for (int kk = 0; kk < 8; ++kk) {
#pragma unroll
            for (int nt = 0; nt < NT; ++nt) {
                int n = C0 + nt * 8 + lq;
                uint32_t b0 = Bcur[n * LDB + kk * 8 + lr];
                uint32_t b1 = Bcur[n * LDB + kk * 8 + 4 + lr];
                MMA_F16(D[nt], aH[kk][0], aH[kk][1], aH[kk][2], aH[kk][3], b0, b1);
                MMA_F16(D[nt], aL[kk][0], aL[kk][1], aL[kk][2], aL[kk][3], b0, b1);
            }
        }

        if (MODE == 0 || MODE == 2) {
            constexpr int SLOT  = (MODE == 0) ? 0 : 1;
            constexpr int CHOFF = (MODE == 0) ? 64 : 0;
            constexpr int MST   = (MODE == 0) ? 32 : 64;
            uint32_t* gdst;
            if (MODE == 0) {
                gdst = g1p + ((size_t)(b * 1024 + (u & 1023)) * 128) * 32;
            } else {
                int h = u & 2047;
                gdst = x1p + ((size_t)(b * 1024 + (h >> 1)) * 128 + (h & 1) * 64) * 64;
            }
#pragma unroll
            for (int half = 0; half < 2; ++half) {
                int r = R0 + lq + half * 8;
                float bias = half ? bias1 : bias0;
                int m = (R0 >> 1) + (lq >> 1) + 4 * half;
                float s = 0.f, q = 0.f;
#pragma unroll
                for (int nt = 0; nt < NT; ++nt) {
                    float v0 = fmaxf(D[nt][half * 2 + 0] + bias, 0.f);
                    float v1 = fmaxf(D[nt][half * 2 + 1] + bias, 0.f);
                    s += v0 + v1; q += v0 * v0 + v1 * v1;
                    float pv0 = __shfl_xor_sync(0xffffffffu, v0, 4);
                    float pv1 = __shfl_xor_sync(0xffffffffu, v1, 4);
                    if (!(lq & 1)) {
                        int col = C0 + nt * 8 + lr * 2;
                        gdst[(size_t)col * MST + m]       = packh(v0, pv0);
                        gdst[(size_t)(col + 1) * MST + m] = packh(v1, pv1);
                    }
                }
                s += __shfl_xor_sync(0xffffffffu, s, 1);
                s += __shfl_xor_sync(0xffffffffu, s, 2);
                q += __shfl_xor_sync(0xffffffffu, q, 1);
                q += __shfl_xor_sync(0xffffffffu, q, 2);
                if (lr == 0) {
                    atomicAdd(&g_sum[SLOT][b][CHOFF + r], (double)s);
                    atomicAdd(&g_sq [SLOT][b][CHOFF + r], (double)q);
                }
            }
        } else if (MODE == 1) {
#pragma unroll
            for (int half = 0; half < 2; ++half) {
                int r = R0 + lq + half * 8;
                float bias = half ? bias1 : bias0;
                float s = 0.f, q = 0.f;
                __half* drow = y3h + (size_t)(b * 128 + r) * CPB + colbase;
#pragma unroll
                for (int nt = 0; nt < NT; ++nt) {
                    float v0 = D[nt][half * 2 + 0] + bias;
                    float v1 = D[nt][half * 2 + 1] + bias;
                    s += v0 + v1; q += v0 * v0 + v1 * v1;
                    *(uint32_t*)(drow + nt * 8 + lr * 2) = packh(v0, v1);
                }
                s += __shfl_xor_sync(0xffffffffu, s, 1);
                s += __shfl_xor_sync(0xffffffffu, s, 2);
                q += __shfl_xor_sync(0xffffffffu, q, 1);
                q += __shfl_xor_sync(0xffffffffu, q, 2);
                if (lr == 0) {
                    atomicAdd(&g_sum[2][b][r], (double)s);
                    atomicAdd(&g_sq [2][b][r], (double)q);
                }
            }
        } else { // MODE 3
#pragma unroll
            for (int half = 0; half < 2; ++half) {
                int c = R0 + lq + half * 8;
                float sc3 = g_scale[2][b][c], sh3 = g_shift[2][b][c];
#pragma unroll
                for (int ni = 0; ni < 2; ++ni) {
                    int n = (colbase >> 5) + ni;
                    int cnt = __ldg(p.count + b * N_ + n);
                    if (cnt < 1) cnt = 1;
                    float v[8];
                    float mx = -3.0e38f;
#pragma unroll
                    for (int nt2 = 0; nt2 < 4; ++nt2) {
#pragma unroll
                        for (int e = 0; e < 2; ++e) {
                            int k = nt2 * 8 + lr * 2 + e;
                            float x = D[ni * 4 + nt2][half * 2 + e];
                            x = (k < cnt) ? x : -1e9f;
                            v[nt2 * 2 + e] = x;
                            mx = fmaxf(mx, x);
                        }
                    }
                    mx = fmaxf(mx, __shfl_xor_sync(0xffffffffu, mx, 1));
                    mx = fmaxf(mx, __shfl_xor_sync(0xffffffffu, mx, 2));
                    const __half* yrow = y3h + (size_t)(b * 128 + c) * CPB + n * 32;
                    float num = 0.f, den = 0.f;
#pragma unroll
                    for (int nt2 = 0; nt2 < 4; ++nt2) {
                        __half2 y2 = *(const __half2*)(yrow + nt2 * 8 + lr * 2);
                        float2 y = __half22float2(y2);
                        float e0 = __expf(v[nt2 * 2 + 0] - mx);
                        float e1 = __expf(v[nt2 * 2 + 1] - mx);
                        float g0 = fmaxf(fmaf(sc3, y.x, sh3), 0.f);
                        float g1 = fmaxf(fmaf(sc3, y.y, sh3), 0.f);
                        num += e0 * g0 + e1 * g1;
                        den += e0 + e1;
                    }
                    num += __shfl_xor_sync(0xffffffffu, num, 1);
                    num += __shfl_xor_sync(0xffffffffu, num, 2);
                    den += __shfl_xor_sync(0xffffffffu, den, 1);
                    den += __shfl_xor_sync(0xffffffffu, den, 2);
                    if (lr == 0)
                        p.out[(size_t)(b * 128 + c) * N_ + n] = num / den;
                }
            }
        }
    };

    // ---- main loops ----------------------------------------------------------
    const int G = gridDim.x;
    int cur_b = unit_b(blockIdx.x);
    build_A(cur_b);

    if (DIRECT) {
        load_direct(blockIdx.x, bh0_u);
        CP_WAIT0();
        __syncthreads();
        int cur = 0;
        for (int u = blockIdx.x; u < UNITS; u += G) {
            int b = unit_b(u);
            if (b != cur_b) { cur_b = b; build_A(b); }
            int un = u + G;
            if (un < UNITS) load_direct(un, cur ? bh0_u : bh1_u);
            run_tile(cur ? Bh1 : Bh0, u);
            CP_WAIT0();
            __syncthreads();
            cur ^= 1;
        }
    } else {
        load_stage(blockIdx.x);
        CP_WAIT0();
        __syncthreads();
        convert();
        __syncthreads();
        for (int u = blockIdx.x; u < UNITS; u += G) {
            int un = u + G;
            if (un < UNITS) load_stage(un);
            run_tile(Bh0, u);
            if (un < UNITS) {
                CP_WAIT0();
                __syncthreads();
                convert();
                __syncthreads();
            }
        }
    }
}

// ---------------------------------------------------------------------------
__global__ void finalize_k(int slot, const float* __restrict__ wgn,
                           const float* __restrict__ bgn) {
    int t = threadIdx.x;
    int b = t >> 7, c = t & 127;
    int g = (c >> 2) << 2;
    double s = g_sum[slot][b][g] + g_sum[slot][b][g + 1] +
               g_sum[slot][b][g + 2] + g_sum[slot][b][g + 3];
    double q = g_sq[slot][b][g] + g_sq[slot][b][g + 1] +
               g_sq[slot][b][g + 2] + g_sq[slot][b][g + 3];
    const double cnte = 4.0 * N_ * K_;
    double mu  = s / cnte;
    double var = q / cnte - mu * mu;
    float rstd = (float)(1.0 / sqrt(var + 1e-5));
    float sc   = wgn[c] * rstd;
    g_scale[slot][b][c] = sc;
    g_shift[slot][b][c] = bgn[c] - (float)mu * sc;
}

// ---------------------------------------------------------------------------
extern "C" void kernel_launch(void* const* d_in, const int* in_sizes, int n_in,
                              void* d_out, int out_size) {
    const float* feat   = (const float*)d_in[0];
    const float* gf     = (const float*)d_in[1];
    const float* gfo    = (const float*)d_in[2];
    const int*   count  = (const int*)  d_in[3];
    const float* W_feat = (const float*)d_in[4];
    const float* b_feat = (const float*)d_in[5];
    const float* W_grp  = (const float*)d_in[6];
    const float* b_grp  = (const float*)d_in[7];
    const float* gn1_w  = (const float*)d_in[8];
    const float* gn1_b  = (const float*)d_in[9];
    const float* W_wc1  = (const float*)d_in[10];
    const float* b_wc1  = (const float*)d_in[11];
    const float* gn2_w  = (const float*)d_in[12];
    const float* gn2_b  = (const float*)d_in[13];
    const float* W_wc2  = (const float*)d_in[14];
    const float* b_wc2  = (const float*)d_in[15];
    const float* W_fo   = (const float*)d_in[16];
    const float* b_fo   = (const float*)d_in[17];
    const float* gn3_w  = (const float*)d_in[18];
    const float* gn3_b  = (const float*)d_in[19];
    float* out = (float*)d_out;

    const int smem0 = 128 * LDB * 4 + 128 * 132 * 4;  // 34816 + 67584 = 102400
    const int smem1 = 64 * LDB * 4 + 128 * 68 * 4;    // 17408 + 34816 = 52224
    const int smemD = 2 * 64 * LDB * 4;               // 34816
    cudaFuncSetAttribute(hmma_k<0>, cudaFuncAttributeMaxDynamicSharedMemorySize, smem0);
    cudaFuncSetAttribute(hmma_k<1>, cudaFuncAttributeMaxDynamicSharedMemorySize, smem1);
    cudaFuncSetAttribute(hmma_k<2>, cudaFuncAttributeMaxDynamicSharedMemorySize, smemD);
    cudaFuncSetAttribute(hmma_k<3>, cudaFuncAttributeMaxDynamicSharedMemorySize, smemD);

    const int GRID = 296;   // 2 CTAs per SM

    zero_stats_k<<<2, 1024>>>();
    feat1_k<<<dim3(N_ / 32, B_), 256>>>(feat, W_feat, b_feat);

    { Ptrs p{gf,  W_grp, b_grp, nullptr, nullptr};
      hmma_k<0><<<GRID, 256, smem0>>>(p); }      // g1p + gn1 stats (ch 64+)
    { Ptrs p{gfo, W_fo,  b_fo,  nullptr, nullptr};
      hmma_k<1><<<GRID, 256, smem1>>>(p); }      // y3h + gn3 stats

    finalize_k<<<1, 512>>>(0, gn1_w, gn1_b);
    finalize_k<<<1, 512>>>(2, gn3_w, gn3_b);

    { Ptrs p{nullptr, W_wc1, b_wc1, nullptr, nullptr};
      hmma_k<2><<<GRID, 256, smemD>>>(p); }      // x1p + gn2 stats

    finalize_k<<<1, 512>>>(1, gn2_w, gn2_b);

    { Ptrs p{nullptr, W_wc2, b_wc2, count, out};
      hmma_k<3><<<GRID, 256, smemD>>>(p); }      // scores -> softmax -> out
}

// round 8
// speedup vs baseline: 6.8463x; 1.0995x over previous
#include <cuda_runtime.h>
#include <cuda_fp16.h>
#include <cstdint>
#include <cstddef>

// ---------------------------------------------------------------------------
constexpr int B_ = 4;
constexpr int N_ = 4096;
constexpr int K_ = 32;
constexpr int CPB = N_ * K_;              // 131072 columns per batch
constexpr int TPB = CPB / 128;            // 1024 full tiles per batch
constexpr int LDB = 68;                   // u32 stride per n-col of B tile

// ---------------------------------------------------------------------------
// Scratch: packed fp16 intermediates (B-fragment layout for direct cp.async)
// ---------------------------------------------------------------------------
__device__ uint32_t feat1p[B_][N_][32];                    //   2 MB
__device__ uint32_t g1p [(size_t)B_ * TPB * 128 * 32];     //  64 MB
__device__ uint32_t x1p [(size_t)B_ * TPB * 128 * 64];     // 128 MB
__device__ __half   y3h [(size_t)B_ * 128 * CPB];          // 128 MB

__device__ double g_sum  [3][B_][128];
__device__ double g_sq   [3][B_][128];
__device__ float  g_scale[3][B_][128];
__device__ float  g_shift[3][B_][128];

// ---------------------------------------------------------------------------
__device__ __forceinline__ uint32_t smem_to_u32(const void* p) {
    uint32_t a;
    asm("{ .reg .u64 t; cvta.to.shared.u64 t, %1; cvt.u32.u64 %0, t; }"
        : "=r"(a) : "l"(p));
    return a;
}
__device__ __forceinline__ void cp_async16(uint32_t dst, const void* src) {
    asm volatile("cp.async.cg.shared.global [%0], [%1], 16;" :: "r"(dst), "l"(src));
}
__device__ __forceinline__ void cp_async16_ca(uint32_t dst, const void* src) {
    asm volatile("cp.async.ca.shared.global [%0], [%1], 16;" :: "r"(dst), "l"(src));
}
#define CP_COMMIT() asm volatile("cp.async.commit_group;" ::: "memory")
#define CP_WAIT0()  asm volatile("cp.async.wait_group 0;" ::: "memory")

#define MMA_F16(d, a0, a1, a2, a3, b0, b1) \
    asm volatile("mma.sync.aligned.m16n8k16.row.col.f32.f16.f16.f32 " \
        "{%0,%1,%2,%3},{%4,%5,%6,%7},{%8,%9},{%0,%1,%2,%3};" \
        : "+f"((d)[0]), "+f"((d)[1]), "+f"((d)[2]), "+f"((d)[3]) \
        : "r"(a0), "r"(a1), "r"(a2), "r"(a3), "r"(b0), "r"(b1))

__device__ __forceinline__ uint32_t packh(float x0, float x1) {
    __half2 h = __float22half2_rn(make_float2(x0, x1));
    return *(uint32_t*)&h;
}
__device__ __forceinline__ void splith(float x0, float x1, uint32_t& hi, uint32_t& lo) {
    __half2 h = __float22half2_rn(make_float2(x0, x1));
    float2 hf = __half22float2(h);
    __half2 l = __float22half2_rn(make_float2(x0 - hf.x, x1 - hf.y));
    hi = *(uint32_t*)&h;
    lo = *(uint32_t*)&l;
}

// ---------------------------------------------------------------------------
__global__ void zero_stats_k() {
    int t = blockIdx.x * blockDim.x + threadIdx.x;
    if (t < 3 * B_ * 128) {
        (&g_sum[0][0][0])[t] = 0.0;
        (&g_sq [0][0][0])[t] = 0.0;
    }
}

// ---------------------------------------------------------------------------
// feat1 = relu(W_feat @ feat + b): packed fp16 into feat1p + gn1 stats (ch<64)
// ---------------------------------------------------------------------------
__global__ void __launch_bounds__(256) feat1_k(const float* __restrict__ feat,
                                               const float* __restrict__ Wf,
                                               const float* __restrict__ bf) {
    __shared__ float Ws[64 * 128];
    __shared__ float Fs[128 * 32];
    const int b  = blockIdx.y;
    const int n0 = blockIdx.x * 32;
    const int tid = threadIdx.x;

    for (int idx = tid; idx < 64 * 128; idx += 256) Ws[idx] = Wf[idx];
    for (int idx = tid; idx < 128 * 32; idx += 256) {
        int c = idx >> 5, jj = idx & 31;
        Fs[idx] = feat[(size_t)(b * 128 + c) * N_ + n0 + jj];
    }
    __syncthreads();

    const int jj = tid & 31;
    const int w  = tid >> 5;
    float acc[8];
#pragma unroll
    for (int oi = 0; oi < 8; ++oi) acc[oi] = __ldg(bf + w * 8 + oi);
#pragma unroll 4
    for (int c = 0; c < 128; ++c) {
        float x = Fs[c * 32 + jj];
#pragma unroll
        for (int oi = 0; oi < 8; ++oi)
            acc[oi] = fmaf(Ws[(w * 8 + oi) * 128 + c], x, acc[oi]);
    }
#pragma unroll
    for (int oi = 0; oi < 8; ++oi) acc[oi] = fmaxf(acc[oi], 0.f);

#pragma unroll
    for (int oi = 0; oi < 8; ++oi) {
        float s = acc[oi], q = acc[oi] * acc[oi];
#pragma unroll
        for (int off = 16; off; off >>= 1) {
            s += __shfl_xor_sync(0xffffffffu, s, off);
            q += __shfl_xor_sync(0xffffffffu, q, off);
        }
        if (jj == 0) {
            atomicAdd(&g_sum[0][b][w * 8 + oi], (double)(32.0f * s));
            atomicAdd(&g_sq [0][b][w * 8 + oi], (double)(32.0f * q));
        }
    }
    uint4 pk;
    pk.x = packh(acc[0], acc[1]);
    pk.y = packh(acc[2], acc[3]);
    pk.z = packh(acc[4], acc[5]);
    pk.w = packh(acc[6], acc[7]);
    *(uint4*)&feat1p[b][n0 + jj][w * 4] = pk;
}

// ---------------------------------------------------------------------------
struct Ptrs {
    const float* X;
    const float* W;
    const float* bias;
    const int*   count;
    float*       out;
};

// MODE 0: g1p = relu(W_grp@gf+b), full tiles (128 col), single-fp16 A
// MODE 1: y3h = W_fo@gfo+b, half tiles (64 col), SPLIT fp16 A (hi+lo)
// MODE 2: x1p = relu(Wwc1*gn1scale @ concat + b'), half tiles, single A
// MODE 3: softmax(Wwc2*gn2scale @ x1p) * relu(gn3(y3h)) summed, single A
template <int MODE>
__global__ void __launch_bounds__(256, 2) hmma_k(Ptrs p) {
    constexpr bool DIRECT = (MODE >= 2);
    constexpr bool SPLIT  = (MODE == 1);           // keep hi+lo only for y3
    constexpr int COLS  = (MODE == 0) ? 128 : 64;
    constexpr int UNITS = B_ * (CPB / COLS);       // 4096 or 8192
    constexpr int NT    = 8;                       // n8 tiles per warp (CW=64)
    constexpr int SPM   = (MODE == 0) ? 132 : 68;  // stage row stride

    extern __shared__ char smem[];
    uint32_t* Bh0 = (uint32_t*)smem;
    uint32_t* Bh1 = Bh0 + COLS * LDB;              // DIRECT double buffer
    float* stage  = (float*)(Bh0 + COLS * LDB);    // !DIRECT
    const uint32_t stage_u = smem_to_u32(stage);
    const uint32_t bh0_u = smem_to_u32(Bh0);
    const uint32_t bh1_u = smem_to_u32(Bh1);

    const int tid = threadIdx.x;
    const int wid = tid >> 5, lane = tid & 31;
    const int lq = lane >> 2, lr = lane & 3;
    const int wrow = (MODE == 0) ? (wid >> 1) : wid;
    const int wcol = (MODE == 0) ? (wid & 1) : 0;
    const int R0 = wrow * 16, C0 = wcol * 64;

    uint32_t aH[8][4];
    uint32_t aL[SPLIT ? 8 : 1][4];
    float bias0 = 0.f, bias1 = 0.f;

    auto build_A = [&](int b) {
        constexpr int SLOT = (MODE == 2) ? 0 : 1;
#pragma unroll
        for (int kk = 0; kk < 8; ++kk) {
            int kb = kk * 16 + lr * 2;
            float s0 = 1.f, s1 = 1.f, s2 = 1.f, s3 = 1.f;
            if (DIRECT) {
                s0 = g_scale[SLOT][b][kb];
                s1 = g_scale[SLOT][b][kb + 1];
                s2 = g_scale[SLOT][b][kb + 8];
                s3 = g_scale[SLOT][b][kb + 9];
            }
            const float* w0 = p.W + (R0 + lq) * 128 + kb;
            const float* w1 = p.W + (R0 + lq + 8) * 128 + kb;
            float2 f0 = *(const float2*)(w0);
            float2 f1 = *(const float2*)(w1);
            float2 f2 = *(const float2*)(w0 + 8);
            float2 f3 = *(const float2*)(w1 + 8);
            if (SPLIT) {
                splith(f0.x * s0, f0.y * s1, aH[kk][0], aL[SPLIT ? kk : 0][0]);
                splith(f1.x * s0, f1.y * s1, aH[kk][1], aL[SPLIT ? kk : 0][1]);
                splith(f2.x * s2, f2.y * s3, aH[kk][2], aL[SPLIT ? kk : 0][2]);
                splith(f3.x * s2, f3.y * s3, aH[kk][3], aL[SPLIT ? kk : 0][3]);
            } else {
                aH[kk][0] = packh(f0.x * s0, f0.y * s1);
                aH[kk][1] = packh(f1.x * s0, f1.y * s1);
                aH[kk][2] = packh(f2.x * s2, f2.y * s3);
                aH[kk][3] = packh(f3.x * s2, f3.y * s3);
            }
        }
        if (MODE == 2) {
            float a0 = 0.f, a1 = 0.f;
            for (int c = lr; c < 128; c += 4) {
                float sh = g_shift[0][b][c];
                a0 = fmaf(__ldg(p.W + (R0 + lq) * 128 + c), sh, a0);
                a1 = fmaf(__ldg(p.W + (R0 + lq + 8) * 128 + c), sh, a1);
            }
            a0 += __shfl_xor_sync(0xffffffffu, a0, 1);
            a0 += __shfl_xor_sync(0xffffffffu, a0, 2);
            a1 += __shfl_xor_sync(0xffffffffu, a1, 1);
            a1 += __shfl_xor_sync(0xffffffffu, a1, 2);
            bias0 = __ldg(p.bias + R0 + lq) + a0;
            bias1 = __ldg(p.bias + R0 + lq + 8) + a1;
        } else if (MODE != 3) {
            bias0 = __ldg(p.bias + R0 + lq);
            bias1 = __ldg(p.bias + R0 + lq + 8);
        }
    };

    // unit decode
    auto unit_b   = [&](int u) { return (MODE == 0) ? (u >> 10) : (u >> 11); };
    auto unit_col = [&](int u) {
        if (MODE == 0) return (u & 1023) << 7;
        int h = u & 2047;
        return (h >> 1) * 128 + (h & 1) * 64;
    };

    auto load_stage = [&](int u) {           // modes 0/1 (fp32 input)
        int b = unit_b(u), colbase = unit_col(u);
        for (int idx = tid; idx < 128 * (COLS / 4); idx += 256) {
            int ch = idx / (COLS / 4), c4 = (idx % (COLS / 4)) << 2;
            cp_async16(stage_u + (uint32_t)(ch * SPM + c4) * 4u,
                       p.X + ((size_t)(b * 128 + ch)) * CPB + colbase + c4);
        }
        CP_COMMIT();
    };

    auto convert = [&]() {                    // stage fp32 -> Bh0 fp16
        for (int s = tid; s < COLS * 4; s += 256) {
            int col = s >> 2, r4 = s & 3;
#pragma unroll
            for (int j = 0; j < 16; ++j) {
                int k = r4 + 4 * j;
                int ch = 2 * k;
                float x0 = stage[ch * SPM + col];
                float x1 = stage[ch * SPM + SPM + col];
                Bh0[col * LDB + k] = packh(x0, x1);
            }
        }
    };

    auto load_direct = [&](int u, uint32_t bh_u) {   // modes 2/3, 64 cols
        int b = unit_b(u);
        int h = u & 2047, tt = h >> 1, half = h & 1;
        if (MODE == 3) {
            const uint32_t* base =
                x1p + ((size_t)(b * 1024 + tt) * 128 + half * 64) * 64;
            for (int idx = tid; idx < 1024; idx += 256) {
                int col = idx >> 4, chunk = idx & 15;
                cp_async16(bh_u + (uint32_t)(col * LDB + chunk * 4) * 4u,
                           base + col * 64 + chunk * 4);
            }
        } else {
            const uint32_t* gbase =
                g1p + ((size_t)(b * 1024 + tt) * 128 + half * 64) * 32;
            int colbase = tt * 128 + half * 64;
            for (int idx = tid; idx < 1024; idx += 256) {
                int col = idx >> 4, chunk = idx & 15;
                if (chunk < 8) {
                    int n = (colbase + col) >> 5;
                    cp_async16_ca(bh_u + (uint32_t)(col * LDB + chunk * 4) * 4u,
                                  &feat1p[b][n][chunk * 4]);
                } else {
                    cp_async16(bh_u + (uint32_t)(col * LDB + 32 + (chunk - 8) * 4) * 4u,
                               gbase + col * 32 + (chunk - 8) * 4);
                }
            }
        }
        CP_COMMIT();
    };

    auto run_tile = [&](uint32_t* Bcur, int u) {
        const int b = unit_b(u), colbase = unit_col(u);

        float D[NT][4];
#pragma unroll
        for (int nt = 0; nt < NT; ++nt)
#pragma unroll
            for (int e = 0; e < 4; ++e) D[nt][e] = 0.f;

#pragma unroll
        for (int kk = 0; kk < 8; ++kk) {
#pragma unroll
            for (int nt = 0; nt < NT; ++nt) {
                int n = C0 + nt * 8 + lq;
                uint32_t b0 = Bcur[n * LDB + kk * 8 + lr];
                uint32_t b1 = Bcur[n * LDB + kk * 8 + 4 + lr];
                MMA_F16(D[nt], aH[kk][0], aH[kk][1], aH[kk][2], aH[kk][3], b0, b1);
                if (SPLIT)
                    MMA_F16(D[nt], aL[SPLIT ? kk : 0][0], aL[SPLIT ? kk : 0][1],
                            aL[SPLIT ? kk : 0][2], aL[SPLIT ? kk : 0][3], b0, b1);
            }
        }

        if (MODE == 0 || MODE == 2) {
            constexpr int SLOT  = (MODE == 0) ? 0 : 1;
            constexpr int CHOFF = (MODE == 0) ? 64 : 0;
            constexpr int MST   = (MODE == 0) ? 32 : 64;
            uint32_t* gdst;
            if (MODE == 0) {
                gdst = g1p + ((size_t)(b * 1024 + (u & 1023)) * 128) * 32;
            } else {
                int h = u & 2047;
                gdst = x1p + ((size_t)(b * 1024 + (h >> 1)) * 128 + (h & 1) * 64) * 64;
            }
#pragma unroll
            for (int half = 0; half < 2; ++half) {
                int r = R0 + lq + half * 8;
                float bias = half ? bias1 : bias0;
                int m = (R0 >> 1) + (lq >> 1) + 4 * half;
                float s = 0.f, q = 0.f;
#pragma unroll
                for (int nt = 0; nt < NT; ++nt) {
                    float v0 = fmaxf(D[nt][half * 2 + 0] + bias, 0.f);
                    float v1 = fmaxf(D[nt][half * 2 + 1] + bias, 0.f);
                    s += v0 + v1; q += v0 * v0 + v1 * v1;
                    float pv0 = __shfl_xor_sync(0xffffffffu, v0, 4);
                    float pv1 = __shfl_xor_sync(0xffffffffu, v1, 4);
                    if (!(lq & 1)) {
                        int col = C0 + nt * 8 + lr * 2;
                        gdst[(size_t)col * MST + m]       = packh(v0, pv0);
                        gdst[(size_t)(col + 1) * MST + m] = packh(v1, pv1);
                    }
                }
                s += __shfl_xor_sync(0xffffffffu, s, 1);
                s += __shfl_xor_sync(0xffffffffu, s, 2);
                q += __shfl_xor_sync(0xffffffffu, q, 1);
                q += __shfl_xor_sync(0xffffffffu, q, 2);
                if (lr == 0) {
                    atomicAdd(&g_sum[SLOT][b][CHOFF + r], (double)s);
                    atomicAdd(&g_sq [SLOT][b][CHOFF + r], (double)q);
                }
            }
        } else if (MODE == 1) {
#pragma unroll
            for (int half = 0; half < 2; ++half) {
                int r = R0 + lq + half * 8;
                float bias = half ? bias1 : bias0;
                float s = 0.f, q = 0.f;
                __half* drow = y3h + (size_t)(b * 128 + r) * CPB + colbase;
#pragma unroll
                for (int nt = 0; nt < NT; ++nt) {
                    float v0 = D[nt][half * 2 + 0] + bias;
                    float v1 = D[nt][half * 2 + 1] + bias;
                    s += v0 + v1; q += v0 * v0 + v1 * v1;
                    *(uint32_t*)(drow + nt * 8 + lr * 2) = packh(v0, v1);
                }
                s += __shfl_xor_sync(0xffffffffu, s, 1);
                s += __shfl_xor_sync(0xffffffffu, s, 2);
                q += __shfl_xor_sync(0xffffffffu, q, 1);
                q += __shfl_xor_sync(0xffffffffu, q, 2);
                if (lr == 0) {
                    atomicAdd(&g_sum[2][b][r], (double)s);
                    atomicAdd(&g_sq [2][b][r], (double)q);
                }
            }
        } else { // MODE 3
#pragma unroll
            for (int half = 0; half < 2; ++half) {
                int c = R0 + lq + half * 8;
                float sc3 = g_scale[2][b][c], sh3 = g_shift[2][b][c];
#pragma unroll
                for (int ni = 0; ni < 2; ++ni) {
                    int n = (colbase >> 5) + ni;
                    int cnt = __ldg(p.count + b * N_ + n);
                    if (cnt < 1) cnt = 1;
                    float v[8];
                    float mx = -3.0e38f;
#pragma unroll
                    for (int nt2 = 0; nt2 < 4; ++nt2) {
#pragma unroll
                        for (int e = 0; e < 2; ++e) {
                            int k = nt2 * 8 + lr * 2 + e;
                            float x = D[ni * 4 + nt2][half * 2 + e];
                            x = (k < cnt) ? x : -1e9f;
                            v[nt2 * 2 + e] = x;
                            mx = fmaxf(mx, x);
                        }
                    }
                    mx = fmaxf(mx, __shfl_xor_sync(0xffffffffu, mx, 1));
                    mx = fmaxf(mx, __shfl_xor_sync(0xffffffffu, mx, 2));
                    const __half* yrow = y3h + (size_t)(b * 128 + c) * CPB + n * 32;
                    float num = 0.f, den = 0.f;
#pragma unroll
                    for (int nt2 = 0; nt2 < 4; ++nt2) {
                        __half2 y2 = *(const __half2*)(yrow + nt2 * 8 + lr * 2);
                        float2 y = __half22float2(y2);
                        float e0 = __expf(v[nt2 * 2 + 0] - mx);
                        float e1 = __expf(v[nt2 * 2 + 1] - mx);
                        float g0 = fmaxf(fmaf(sc3, y.x, sh3), 0.f);
                        float g1 = fmaxf(fmaf(sc3, y.y, sh3), 0.f);
                        num += e0 * g0 + e1 * g1;
                        den += e0 + e1;
                    }
                    num += __shfl_xor_sync(0xffffffffu, num, 1);
                    num += __shfl_xor_sync(0xffffffffu, num, 2);
                    den += __shfl_xor_sync(0xffffffffu, den, 1);
                    den += __shfl_xor_sync(0xffffffffu, den, 2);
                    if (lr == 0)
                        p.out[(size_t)(b * 128 + c) * N_ + n] = num / den;
                }
            }
        }
    };

    // ---- main loops ----------------------------------------------------------
    const int G = gridDim.x;
    int cur_b = unit_b(blockIdx.x);
    build_A(cur_b);

    if (DIRECT) {
        load_direct(blockIdx.x, bh0_u);
        CP_WAIT0();
        __syncthreads();
        int cur = 0;
        for (int u = blockIdx.x; u < UNITS; u += G) {
            int b = unit_b(u);
            if (b != cur_b) { cur_b = b; build_A(b); }
            int un = u + G;
            if (un < UNITS) load_direct(un, cur ? bh0_u : bh1_u);
            run_tile(cur ? Bh1 : Bh0, u);
            CP_WAIT0();
            __syncthreads();
            cur ^= 1;
        }
    } else {
        load_stage(blockIdx.x);
        CP_WAIT0();
        __syncthreads();
        convert();
        __syncthreads();
        for (int u = blockIdx.x; u < UNITS; u += G) {
            int un = u + G;
            if (un < UNITS) load_stage(un);
            run_tile(Bh0, u);
            if (un < UNITS) {
                CP_WAIT0();
                __syncthreads();
                convert();
                __syncthreads();
            }
        }
    }
}

// ---------------------------------------------------------------------------
__global__ void finalize_k(int slot, const float* __restrict__ wgn,
                           const float* __restrict__ bgn) {
    int t = threadIdx.x;
    int b = t >> 7, c = t & 127;
    int g = (c >> 2) << 2;
    double s = g_sum[slot][b][g] + g_sum[slot][b][g + 1] +
               g_sum[slot][b][g + 2] + g_sum[slot][b][g + 3];
    double q = g_sq[slot][b][g] + g_sq[slot][b][g + 1] +
               g_sq[slot][b][g + 2] + g_sq[slot][b][g + 3];
    const double cnte = 4.0 * N_ * K_;
    double mu  = s / cnte;
    double var = q / cnte - mu * mu;
    float rstd = (float)(1.0 / sqrt(var + 1e-5));
    float sc   = wgn[c] * rstd;
    g_scale[slot][b][c] = sc;
    g_shift[slot][b][c] = bgn[c] - (float)mu * sc;
}

// ---------------------------------------------------------------------------
extern "C" void kernel_launch(void* const* d_in, const int* in_sizes, int n_in,
                              void* d_out, int out_size) {
    const float* feat   = (const float*)d_in[0];
    const float* gf     = (const float*)d_in[1];
    const float* gfo    = (const float*)d_in[2];
    const int*   count  = (const int*)  d_in[3];
    const float* W_feat = (const float*)d_in[4];
    const float* b_feat = (const float*)d_in[5];
    const float* W_grp  = (const float*)d_in[6];
    const float* b_grp  = (const float*)d_in[7];
    const float* gn1_w  = (const float*)d_in[8];
    const float* gn1_b  = (const float*)d_in[9];
    const float* W_wc1  = (const float*)d_in[10];
    const float* b_wc1  = (const float*)d_in[11];
    const float* gn2_w  = (const float*)d_in[12];
    const float* gn2_b  = (const float*)d_in[13];
    const float* W_wc2  = (const float*)d_in[14];
    const float* b_wc2  = (const float*)d_in[15];
    const float* W_fo   = (const float*)d_in[16];
    const float* b_fo   = (const float*)d_in[17];
    const float* gn3_w  = (const float*)d_in[18];
    const float* gn3_b  = (const float*)d_in[19];
    float* out = (float*)d_out;

    const int smem0 = 128 * LDB * 4 + 128 * 132 * 4;  // 34816 + 67584 = 102400
    const int smem1 = 64 * LDB * 4 + 128 * 68 * 4;    // 17408 + 34816 = 52224
    const int smemD = 2 * 64 * LDB * 4;               // 34816
    cudaFuncSetAttribute(hmma_k<0>, cudaFuncAttributeMaxDynamicSharedMemorySize, smem0);
    cudaFuncSetAttribute(hmma_k<1>, cudaFuncAttributeMaxDynamicSharedMemorySize, smem1);
    cudaFuncSetAttribute(hmma_k<2>, cudaFuncAttributeMaxDynamicSharedMemorySize, smemD);
    cudaFuncSetAttribute(hmma_k<3>, cudaFuncAttributeMaxDynamicSharedMemorySize, smemD);

    const int GRID = 296;   // 2 CTAs per SM

    zero_stats_k<<<2, 1024>>>();
    feat1_k<<<dim3(N_ / 32, B_), 256>>>(feat, W_feat, b_feat);

    { Ptrs p{gf,  W_grp, b_grp, nullptr, nullptr};
      hmma_k<0><<<GRID, 256, smem0>>>(p); }      // g1p + gn1 stats (ch 64+)
    { Ptrs p{gfo, W_fo,  b_fo,  nullptr, nullptr};
      hmma_k<1><<<GRID, 256, smem1>>>(p); }      // y3h + gn3 stats

    finalize_k<<<1, 512>>>(0, gn1_w, gn1_b);
    finalize_k<<<1, 512>>>(2, gn3_w, gn3_b);

    { Ptrs p{nullptr, W_wc1, b_wc1, nullptr, nullptr};
      hmma_k<2><<<GRID, 256, smemD>>>(p); }      // x1p + gn2 stats

    finalize_k<<<1, 512>>>(1, gn2_w, gn2_b);

    { Ptrs p{nullptr, W_wc2, b_wc2, count, out};
      hmma_k<3><<<GRID, 256, smemD>>>(p); }      // scores -> softmax -> out
}